// round 15
// baseline (speedup 1.0000x reference)
#include <cuda_runtime.h>
#include <cuda_fp16.h>
#include <math.h>
#include <stdint.h>

// ---------------- problem sizes ----------------
#define NA 50000
#define NP 100000
#define HC 128
#define NH 8
#define EW 400000
#define ER 400000
#define EC 800000
#define EP (EW + EC)
#define BN_EPS 1e-5f

// ---------------- scratch layout (float units) ----------------
#define OFF_XA    0ull
#define OFF_XP    (OFF_XA   + (size_t)NA*128)
#define OFF_A384  (OFF_XP   + (size_t)NP*128)        // half[NA*384] : Q | K_rel0 | V_rel0
#define OFF_P640  (OFF_A384 + (size_t)NA*192)        // half[NP*640] : Q | K_rel2 | V_rel2 | K_rel1 | V_rel1
#define OFF_AGGA  (OFF_P640 + (size_t)NP*320)
#define OFF_AGGP  (OFF_AGGA + (size_t)NA*128)
#define OFF_TMPA  (OFF_AGGP + (size_t)NP*128)
#define OFF_TMPP  (OFF_TMPA + (size_t)NA*128)
#define OFF_WA    (OFF_TMPP + (size_t)NP*128)        // 2 * 128 * 384
#define OFF_WP    (OFF_WA   + 2ull*128*384)          // 2 * 128 * 640
#define OFF_WAB   (OFF_WP   + 2ull*128*640)          // 2 * 384
#define OFF_WPB   (OFF_WAB  + 2ull*384)              // 2 * 640
#define OFF_STATS (OFF_WPB  + 2ull*640)              // 2 layers * 512
// integer region
#define OFF_INT   (OFF_STATS + 1024ull)
#define IOFF_ROWP 0ull
#define IOFF_ROWA (IOFF_ROWP + NP + 1)
#define IOFF_CURP (IOFF_ROWA + NA + 1)
#define IOFF_CURA (IOFF_CURP + NP)
#define IOFF_SRCP (IOFF_CURA + NA)
#define IOFF_SRCA (IOFF_SRCP + EP)
#define IOFF_BS   (IOFF_SRCA + ER)
#define INT_TOTAL (IOFF_BS + 256)
#define TOTAL_FLOATS (OFF_INT + INT_TOTAL + 64ull)

__device__ float g_scratch[TOTAL_FLOATS];

// ---------------- tf32 helpers ----------------
__device__ __forceinline__ uint32_t f2tf32(float x)
{
    uint32_t r;
    asm("cvt.rna.tf32.f32 %0, %1;" : "=r"(r) : "f"(x));
    return r;
}

__device__ __forceinline__ void mma_tf32(float4& c, const uint32_t* a, const uint32_t* b)
{
    asm volatile(
        "mma.sync.aligned.m16n8k8.row.col.f32.tf32.tf32.f32 "
        "{%0,%1,%2,%3}, {%4,%5,%6,%7}, {%8,%9}, {%0,%1,%2,%3};"
        : "+f"(c.x), "+f"(c.y), "+f"(c.z), "+f"(c.w)
        : "r"(a[0]), "r"(a[1]), "r"(a[2]), "r"(a[3]), "r"(b[0]), "r"(b[1]));
}

__device__ __forceinline__ float4 ld4h(const __half* p)
{
    __half2 a = *(const __half2*)p;
    __half2 b = *(const __half2*)(p + 2);
    float2 fa = __half22float2(a), fb = __half22float2(b);
    return make_float4(fa.x, fa.y, fb.x, fb.y);
}

// ---------------- dual-problem tf32x2 GEMM (protected; R14 byte-identical) -------
__global__ void __launch_bounds__(256)
gemm2(const float* __restrict__ A0, int lda0, const float* __restrict__ W0, int ldw0,
      const float* __restrict__ b0, float* __restrict__ C0, __half* __restrict__ Ch0,
      int ldc0, int M0, int gx0, const float* __restrict__ x0, const float* __restrict__ s0,
      const float* __restrict__ A1, int lda1, const float* __restrict__ W1, int ldw1,
      const float* __restrict__ b1, float* __restrict__ C1, __half* __restrict__ Ch1,
      int ldc1, int M1, int gx1, const float* __restrict__ x1, const float* __restrict__ s1,
      int gy1, int act)
{
    __shared__ uint32_t As[128][20];
    __shared__ uint32_t Bs[16][136], Bl[16][136];

    const float* A; const float* W; const float* bias; float* C; __half* Ch;
    const float* xold; const float* skipv;
    int lda, ldw, ldc, M, gx, bm;
    if ((int)blockIdx.y < gy1) {
        A = A0; W = W0; bias = b0; C = C0; Ch = Ch0; xold = x0; skipv = s0;
        lda = lda0; ldw = ldw0; ldc = ldc0; M = M0; gx = gx0;
        bm = blockIdx.y * 128;
    } else {
        A = A1; W = W1; bias = b1; C = C1; Ch = Ch1; xold = x1; skipv = s1;
        lda = lda1; ldw = ldw1; ldc = ldc1; M = M1; gx = gx1;
        bm = (blockIdx.y - gy1) * 128;
    }
    if ((int)blockIdx.x >= gx) return;

    const int bn = blockIdx.x * 128;
    const int tid = threadIdx.x;
    const int lane = tid & 31;
    const int warp = tid >> 5;
    const int wm = warp >> 2;
    const int wn = warp & 3;

    float4 acc[4][4];
#pragma unroll
    for (int i = 0; i < 4; i++)
#pragma unroll
        for (int j = 0; j < 4; j++) acc[i][j] = make_float4(0.f, 0.f, 0.f, 0.f);

    for (int k0 = 0; k0 < 128; k0 += 16) {
#pragma unroll
        for (int i = 0; i < 2; i++) {
            int id  = tid + i * 256;
            int row = id >> 2;
            int kc  = (id & 3) * 4;
            int grow = bm + row;
            float4 v = make_float4(0.f, 0.f, 0.f, 0.f);
            if (grow < M) v = *(const float4*)(A + (size_t)grow * lda + k0 + kc);
            As[row][kc + 0] = f2tf32(v.x); As[row][kc + 1] = f2tf32(v.y);
            As[row][kc + 2] = f2tf32(v.z); As[row][kc + 3] = f2tf32(v.w);
        }
#pragma unroll
        for (int i = 0; i < 2; i++) {
            int id  = tid + i * 256;
            int row = id >> 5;
            int col = (id & 31) * 4;
            float4 v = *(const float4*)(W + (size_t)(k0 + row) * ldw + bn + col);
            uint32_t h;
            h = f2tf32(v.x); Bs[row][col + 0] = h; Bl[row][col + 0] = f2tf32(v.x - __uint_as_float(h));
            h = f2tf32(v.y); Bs[row][col + 1] = h; Bl[row][col + 1] = f2tf32(v.y - __uint_as_float(h));
            h = f2tf32(v.z); Bs[row][col + 2] = h; Bl[row][col + 2] = f2tf32(v.z - __uint_as_float(h));
            h = f2tf32(v.w); Bs[row][col + 3] = h; Bl[row][col + 3] = f2tf32(v.w - __uint_as_float(h));
        }
        __syncthreads();

#pragma unroll
        for (int ks = 0; ks < 16; ks += 8) {
            uint32_t af[4][4];
            const int kc = ks + (lane & 3);
#pragma unroll
            for (int mf = 0; mf < 4; mf++) {
                int r = wm * 64 + mf * 16 + (lane >> 2);
                af[mf][0] = As[r][kc];
                af[mf][1] = As[r + 8][kc];
                af[mf][2] = As[r][kc + 4];
                af[mf][3] = As[r + 8][kc + 4];
            }
            uint32_t bh[4][2], bl[4][2];
#pragma unroll
            for (int nf = 0; nf < 4; nf++) {
                int n = wn * 32 + nf * 8 + (lane >> 2);
                bh[nf][0] = Bs[kc][n];     bl[nf][0] = Bl[kc][n];
                bh[nf][1] = Bs[kc + 4][n]; bl[nf][1] = Bl[kc + 4][n];
            }
#pragma unroll
            for (int mf = 0; mf < 4; mf++)
#pragma unroll
                for (int nf = 0; nf < 4; nf++) {
                    mma_tf32(acc[mf][nf], af[mf], bl[nf]);
                    mma_tf32(acc[mf][nf], af[mf], bh[nf]);
                }
        }
        __syncthreads();
    }

    const int lr = lane >> 2;
    const int lc = (lane & 3) * 2;
    float sk = 0.f;
    if (act == 2) sk = 1.f / (1.f + __expf(-skipv[0]));
    float2 bv[4];
#pragma unroll
    for (int nf = 0; nf < 4; nf++) {
        int c0 = bn + wn * 32 + nf * 8 + lc;
        bv[nf] = *(const float2*)(bias + c0);
    }
#pragma unroll
    for (int mf = 0; mf < 4; mf++) {
        int r0 = bm + wm * 64 + mf * 16 + lr;
        int r1 = r0 + 8;
#pragma unroll
        for (int nf = 0; nf < 4; nf++) {
            int c0 = bn + wn * 32 + nf * 8 + lc;
            float4 a = acc[mf][nf];
            float2 o0 = make_float2(a.x + bv[nf].x, a.y + bv[nf].y);
            float2 o1 = make_float2(a.z + bv[nf].x, a.w + bv[nf].y);
            if (act == 1) {
                o0.x = fmaxf(o0.x, 0.f); o0.y = fmaxf(o0.y, 0.f);
                o1.x = fmaxf(o1.x, 0.f); o1.y = fmaxf(o1.y, 0.f);
            } else if (act == 2) {
                if (r0 < M) {
                    float2 xv = *(const float2*)(xold + (size_t)r0 * ldc + c0);
                    o0.x = sk * o0.x + (1.f - sk) * xv.x;
                    o0.y = sk * o0.y + (1.f - sk) * xv.y;
                }
                if (r1 < M) {
                    float2 xv = *(const float2*)(xold + (size_t)r1 * ldc + c0);
                    o1.x = sk * o1.x + (1.f - sk) * xv.x;
                    o1.y = sk * o1.y + (1.f - sk) * xv.y;
                }
            }
            if (Ch) {
                if (r0 < M) *(__half2*)(Ch + (size_t)r0 * ldc + c0) = __floats2half2_rn(o0.x, o0.y);
                if (r1 < M) *(__half2*)(Ch + (size_t)r1 * ldc + c0) = __floats2half2_rn(o1.x, o1.y);
            } else {
                if (r0 < M) *(float2*)(C + (size_t)r0 * ldc + c0) = o0;
                if (r1 < M) *(float2*)(C + (size_t)r1 * ldc + c0) = o1;
            }
        }
    }
}

// ---------------- merged composite weights (A then P in one launch) --------
#define WA_TOT (2 * 128 * 384)
#define WP_TOT (2 * 128 * 640)
__global__ void wcomp_all(const float* __restrict__ kqv_W, const float* __restrict__ a_k,
                          const float* __restrict__ a_v, float* __restrict__ WA,
                          float* __restrict__ WP)
{
    int gid = blockIdx.x * blockDim.x + threadIdx.x;
    if (gid < WA_TOT) {
        int l = gid / (128 * 384);
        int rem = gid % (128 * 384);
        int r = rem / 384, c = rem % 384;
        const float* Wrow = kqv_W + (size_t)(l * 2 + 0) * 128 * 384 + (size_t)r * 384;
        float s;
        if (c < 128) {
            s = Wrow[128 + c];
        } else {
            int cc = c - 128;
            int c2 = cc & 127, h = c2 >> 4, e = c2 & 15;
            const float* Wb = Wrow + ((cc < 128) ? 0 : 256);
            const float* Am = ((cc < 128) ? a_k : a_v) + (size_t)(l * 3 + 0) * 2048 + h * 256 + e;
            s = 0.f;
#pragma unroll
            for (int dd = 0; dd < 16; dd++) s += Wb[h * 16 + dd] * Am[dd * 16];
        }
        WA[gid] = s;
    } else {
        int g = gid - WA_TOT;
        if (g >= WP_TOT) return;
        int l = g / (128 * 640);
        int rem = g % (128 * 640);
        int r = rem / 640, c = rem % 640;
        const float* Wrow = kqv_W + (size_t)(l * 2 + 1) * 128 * 384 + (size_t)r * 384;
        float s;
        if (c < 128) {
            s = Wrow[128 + c];
        } else {
            int rel = (c < 384) ? 2 : 1;
            int cc = (c < 384) ? (c - 128) : (c - 384);
            int c2 = cc & 127, h = c2 >> 4, e = c2 & 15;
            const float* Wb = Wrow + ((cc < 128) ? 0 : 256);
            const float* Am = ((cc < 128) ? a_k : a_v) + (size_t)(l * 3 + rel) * 2048 + h * 256 + e;
            s = 0.f;
#pragma unroll
            for (int dd = 0; dd < 16; dd++) s += Wb[h * 16 + dd] * Am[dd * 16];
        }
        WP[g] = s;
    }
}

__global__ void bcomp_all(const float* __restrict__ kqv_b, const float* __restrict__ a_k,
                          const float* __restrict__ a_v, float* __restrict__ WAB,
                          float* __restrict__ WPB)
{
    int gid = blockIdx.x * blockDim.x + threadIdx.x;
    if (gid < 2 * 384) {
        int l = gid / 384, c = gid % 384;
        const float* brow = kqv_b + (size_t)(l * 2 + 0) * 384;
        float s;
        if (c < 128) {
            s = brow[128 + c];
        } else {
            int cc = c - 128;
            int c2 = cc & 127, h = c2 >> 4, e = c2 & 15;
            const float* bb = brow + ((cc < 128) ? 0 : 256);
            const float* Am = ((cc < 128) ? a_k : a_v) + (size_t)(l * 3 + 0) * 2048 + h * 256 + e;
            s = 0.f;
#pragma unroll
            for (int dd = 0; dd < 16; dd++) s += bb[h * 16 + dd] * Am[dd * 16];
        }
        WAB[gid] = s;
    } else {
        int g = gid - 2 * 384;
        if (g >= 2 * 640) return;
        int l = g / 640, c = g % 640;
        const float* brow = kqv_b + (size_t)(l * 2 + 1) * 384;
        float s;
        if (c < 128) {
            s = brow[128 + c];
        } else {
            int rel = (c < 384) ? 2 : 1;
            int cc = (c < 384) ? (c - 128) : (c - 384);
            int c2 = cc & 127, h = c2 >> 4, e = c2 & 15;
            const float* bb = brow + ((cc < 128) ? 0 : 256);
            const float* Am = ((cc < 128) ? a_k : a_v) + (size_t)(l * 3 + rel) * 2048 + h * 256 + e;
            s = 0.f;
#pragma unroll
            for (int dd = 0; dd < 16; dd++) s += bb[h * 16 + dd] * Am[dd * 16];
        }
        WPB[g] = s;
    }
}

// ---------------- CSR build (merged launches) ----------------
__global__ void hist3(const int* __restrict__ wdst, const int* __restrict__ cdst,
                      const int* __restrict__ rdst, int* __restrict__ degP,
                      int* __restrict__ degA)
{
    int i = blockIdx.x * blockDim.x + threadIdx.x;
    if (i < EW) atomicAdd(&degP[wdst[i]], 1);
    else if (i < EW + EC) atomicAdd(&degP[cdst[i - EW]], 1);
    else if (i < EW + EC + ER) atomicAdd(&degA[rdst[i - EW - EC]], 1);
}

__global__ void scatter3(const int* __restrict__ wsrc, const int* __restrict__ wdst,
                         const int* __restrict__ csrc, const int* __restrict__ cdst,
                         const int* __restrict__ rsrc, const int* __restrict__ rdst,
                         int* __restrict__ curP, int* __restrict__ curA,
                         int* __restrict__ outP, int* __restrict__ outA)
{
    int i = blockIdx.x * blockDim.x + threadIdx.x;
    if (i < EW) {
        int p = atomicAdd(&curP[wdst[i]], 1);
        outP[p] = wsrc[i];
    } else if (i < EW + EC) {
        int k = i - EW;
        int p = atomicAdd(&curP[cdst[k]], 1);
        outP[p] = csrc[k] + NA;
    } else if (i < EW + EC + ER) {
        int k = i - EW - EC;
        int p = atomicAdd(&curA[rdst[k]], 1);
        outA[p] = rsrc[k];
    }
}

// dual-problem partial scan: blocks [0,nbP) process P, [nbP, nbP+nbA) process A.
// bsums regions: P at BS[0..], A at BS[128..].
__global__ void scan_partial2(const int* __restrict__ degP, int* __restrict__ rowP,
                              const int* __restrict__ degA, int* __restrict__ rowA,
                              int* __restrict__ bsums, int nbPb)
{
    __shared__ int warpsum[8];
    const int* deg; int* row; int* bs; int n; int bid;
    if ((int)blockIdx.x < nbPb) { deg = degP; row = rowP; bs = bsums; n = NP; bid = blockIdx.x; }
    else { deg = degA; row = rowA; bs = bsums + 128; n = NA; bid = blockIdx.x - nbPb; }
    int t = threadIdx.x;
    int lane = t & 31, wid = t >> 5;
    int base = bid * 1024 + t * 4;
    int v0 = (base + 0 < n) ? deg[base + 0] : 0;
    int v1 = (base + 1 < n) ? deg[base + 1] : 0;
    int v2 = (base + 2 < n) ? deg[base + 2] : 0;
    int v3 = (base + 3 < n) ? deg[base + 3] : 0;
    int e0 = 0, e1 = v0, e2 = e1 + v1, e3 = e2 + v2;
    int tot = e3 + v3;
    int inc = tot;
#pragma unroll
    for (int off = 1; off < 32; off <<= 1) {
        int y = __shfl_up_sync(0xffffffffu, inc, off);
        if (lane >= off) inc += y;
    }
    if (lane == 31) warpsum[wid] = inc;
    __syncthreads();
    if (wid == 0) {
        int w = (lane < 8) ? warpsum[lane] : 0;
#pragma unroll
        for (int off = 1; off < 8; off <<= 1) {
            int y = __shfl_up_sync(0xffffffffu, w, off);
            if (lane >= off) w += y;
        }
        if (lane < 8) warpsum[lane] = w;
    }
    __syncthreads();
    int warpExcl = (wid == 0) ? 0 : warpsum[wid - 1];
    int thrExcl = warpExcl + inc - tot;
    if (base + 0 < n) row[base + 0] = thrExcl + e0;
    if (base + 1 < n) row[base + 1] = thrExcl + e1;
    if (base + 2 < n) row[base + 2] = thrExcl + e2;
    if (base + 3 < n) row[base + 3] = thrExcl + e3;
    if (t == 0) bs[bid] = warpsum[7];
}

// two blocks: block 0 scans P bsums (nbP entries), block 1 scans A bsums.
__global__ void scan_small2(int* __restrict__ bsums, int nbPb, int nbAb)
{
    __shared__ int warpsum[8];
    int* bs = (blockIdx.x == 0) ? bsums : bsums + 128;
    int nb = (blockIdx.x == 0) ? nbPb : nbAb;
    int t = threadIdx.x;
    int lane = t & 31, wid = t >> 5;
    int v = (t < nb) ? bs[t] : 0;
    int inc = v;
#pragma unroll
    for (int off = 1; off < 32; off <<= 1) {
        int y = __shfl_up_sync(0xffffffffu, inc, off);
        if (lane >= off) inc += y;
    }
    if (lane == 31) warpsum[wid] = inc;
    __syncthreads();
    if (wid == 0) {
        int w = (lane < 8) ? warpsum[lane] : 0;
#pragma unroll
        for (int off = 1; off < 8; off <<= 1) {
            int y = __shfl_up_sync(0xffffffffu, w, off);
            if (lane >= off) w += y;
        }
        if (lane < 8) warpsum[lane] = w;
    }
    __syncthreads();
    int warpExcl = (wid == 0) ? 0 : warpsum[wid - 1];
    int excl = warpExcl + inc - v;
    if (t < nb) bs[t] = excl;
    if (t == 255) bs[nb] = warpExcl + inc;
}

// add offsets + cursor init for both problems in one launch.
__global__ void add_off2(int* __restrict__ rowP, int* __restrict__ curP,
                         int* __restrict__ rowA, int* __restrict__ curA,
                         const int* __restrict__ bsums, int nbPb, int nbAb)
{
    int i = blockIdx.x * blockDim.x + threadIdx.x;
    if (i < NP) {
        int r = rowP[i] + bsums[i >> 10];
        rowP[i] = r;
        curP[i] = r;
        if (i == 0) rowP[NP] = bsums[nbPb];
    } else {
        int k = i - NP;
        if (k >= NA) return;
        int r = rowA[k] + bsums[128 + (k >> 10)];
        rowA[k] = r;
        curA[k] = r;
        if (k == 0) rowA[NA] = bsums[128 + nbAb];
    }
}

// ---------------- fused attention (protected; R14 byte-identical) ----
__global__ void attn_agg2(const __half* __restrict__ A384, const __half* __restrict__ P640,
                          const int* __restrict__ rowP, const int* __restrict__ srcP,
                          const float* __restrict__ prel0, const float* __restrict__ prel2,
                          const int* __restrict__ rowA, const int* __restrict__ srcA,
                          const float* __restrict__ prel1,
                          float* __restrict__ aggP, float* __restrict__ aggA)
{
    int gwarp = (blockIdx.x * blockDim.x + threadIdx.x) >> 5;
    int lane = threadIdx.x & 31;
    if (gwarp >= NP + NA) return;
    int h = lane >> 2;
    int c = h * 16 + (lane & 3) * 4;

    float m = -INFINITY, s = 0.f;
    float4 acc = make_float4(0.f, 0.f, 0.f, 0.f);

    if (gwarp < NP) {
        int node = gwarp;
        float4 q4 = ld4h(P640 + (size_t)node * 640 + c);
        float pA = prel0[h] * 0.25f;
        float pB = prel2[h] * 0.25f;
        int js = rowP[node], je = rowP[node + 1];
        int j = js;
        for (; j + 1 < je; j += 2) {
            int sr1 = srcP[j];
            int sr2 = srcP[j + 1];
            const __half* kv1 = (sr1 < NA) ? (A384 + (size_t)sr1 * 384 + 128)
                                           : (P640 + (size_t)(sr1 - NA) * 640 + 128);
            const __half* kv2 = (sr2 < NA) ? (A384 + (size_t)sr2 * 384 + 128)
                                           : (P640 + (size_t)(sr2 - NA) * 640 + 128);
            float4 k1 = ld4h(kv1 + c);
            float4 k2 = ld4h(kv2 + c);
            float p1 = q4.x * k1.x + q4.y * k1.y + q4.z * k1.z + q4.w * k1.w;
            float p2 = q4.x * k2.x + q4.y * k2.y + q4.z * k2.z + q4.w * k2.w;
            p1 += __shfl_xor_sync(0xffffffffu, p1, 1);
            p2 += __shfl_xor_sync(0xffffffffu, p2, 1);
            p1 += __shfl_xor_sync(0xffffffffu, p1, 2);
            p2 += __shfl_xor_sync(0xffffffffu, p2, 2);
            float a1 = p1 * ((sr1 < NA) ? pA : pB);
            float a2 = p2 * ((sr2 < NA) ? pA : pB);
            float4 v1 = ld4h(kv1 + 128 + c);
            float4 v2 = ld4h(kv2 + 128 + c);
            float newm = fmaxf(m, fmaxf(a1, a2));
            float scl = __expf(m - newm);
            float w1 = __expf(a1 - newm);
            float w2 = __expf(a2 - newm);
            s = s * scl + w1 + w2;
            acc.x = acc.x * scl + w1 * v1.x + w2 * v2.x;
            acc.y = acc.y * scl + w1 * v1.y + w2 * v2.y;
            acc.z = acc.z * scl + w1 * v1.z + w2 * v2.z;
            acc.w = acc.w * scl + w1 * v1.w + w2 * v2.w;
            m = newm;
        }
        for (; j < je; j++) {
            int sr = srcP[j];
            const __half* kv = (sr < NA) ? (A384 + (size_t)sr * 384 + 128)
                                         : (P640 + (size_t)(sr - NA) * 640 + 128);
            float4 k1 = ld4h(kv + c);
            float part = q4.x * k1.x + q4.y * k1.y + q4.z * k1.z + q4.w * k1.w;
            part += __shfl_xor_sync(0xffffffffu, part, 1);
            part += __shfl_xor_sync(0xffffffffu, part, 2);
            float a = part * ((sr < NA) ? pA : pB);
            float newm = fmaxf(m, a);
            float scl = __expf(m - newm);
            float w = __expf(a - newm);
            s = s * scl + w;
            float4 v1 = ld4h(kv + 128 + c);
            acc.x = acc.x * scl + w * v1.x;
            acc.y = acc.y * scl + w * v1.y;
            acc.z = acc.z * scl + w * v1.z;
            acc.w = acc.w * scl + w * v1.w;
            m = newm;
        }
        float inv = 1.f / (s + 1e-16f);
        float4 r;
        float v;
        v = acc.x * inv; r.x = 0.5f * v * (1.f + erff(v * 0.70710678118654752f));
        v = acc.y * inv; r.y = 0.5f * v * (1.f + erff(v * 0.70710678118654752f));
        v = acc.z * inv; r.z = 0.5f * v * (1.f + erff(v * 0.70710678118654752f));
        v = acc.w * inv; r.w = 0.5f * v * (1.f + erff(v * 0.70710678118654752f));
        *(float4*)(aggP + (size_t)node * 128 + c) = r;
    } else {
        int node = gwarp - NP;
        float4 q4 = ld4h(A384 + (size_t)node * 384 + c);
        float pr = prel1[h] * 0.25f;
        int js = rowA[node], je = rowA[node + 1];
        int j = js;
        for (; j + 1 < je; j += 2) {
            int s1 = srcA[j];
            int s2 = srcA[j + 1];
            const __half* kv1 = P640 + (size_t)s1 * 640 + 384;
            const __half* kv2 = P640 + (size_t)s2 * 640 + 384;
            float4 k1 = ld4h(kv1 + c);
            float4 k2 = ld4h(kv2 + c);
            float p1 = q4.x * k1.x + q4.y * k1.y + q4.z * k1.z + q4.w * k1.w;
            float p2 = q4.x * k2.x + q4.y * k2.y + q4.z * k2.z + q4.w * k2.w;
            p1 += __shfl_xor_sync(0xffffffffu, p1, 1);
            p2 += __shfl_xor_sync(0xffffffffu, p2, 1);
            p1 += __shfl_xor_sync(0xffffffffu, p1, 2);
            p2 += __shfl_xor_sync(0xffffffffu, p2, 2);
            float a1 = p1 * pr;
            float a2 = p2 * pr;
            float4 v1 = ld4h(kv1 + 128 + c);
            float4 v2 = ld4h(kv2 + 128 + c);
            float newm = fmaxf(m, fmaxf(a1, a2));
            float scl = __expf(m - newm);
            float w1 = __expf(a1 - newm);
            float w2 = __expf(a2 - newm);
            s = s * scl + w1 + w2;
            acc.x = acc.x * scl + w1 * v1.x + w2 * v2.x;
            acc.y = acc.y * scl + w1 * v1.y + w2 * v2.y;
            acc.z = acc.z * scl + w1 * v1.z + w2 * v2.z;
            acc.w = acc.w * scl + w1 * v1.w + w2 * v2.w;
            m = newm;
        }
        for (; j < je; j++) {
            int s1 = srcA[j];
            const __half* kv = P640 + (size_t)s1 * 640 + 384;
            float4 k1 = ld4h(kv + c);
            float part = q4.x * k1.x + q4.y * k1.y + q4.z * k1.z + q4.w * k1.w;
            part += __shfl_xor_sync(0xffffffffu, part, 1);
            part += __shfl_xor_sync(0xffffffffu, part, 2);
            float a = part * pr;
            float newm = fmaxf(m, a);
            float scl = __expf(m - newm);
            float w = __expf(a - newm);
            s = s * scl + w;
            float4 v1 = ld4h(kv + 128 + c);
            acc.x = acc.x * scl + w * v1.x;
            acc.y = acc.y * scl + w * v1.y;
            acc.z = acc.z * scl + w * v1.z;
            acc.w = acc.w * scl + w * v1.w;
            m = newm;
        }
        float inv = 1.f / (s + 1e-16f);
        float4 r;
        float v;
        v = acc.x * inv; r.x = 0.5f * v * (1.f + erff(v * 0.70710678118654752f));
        v = acc.y * inv; r.y = 0.5f * v * (1.f + erff(v * 0.70710678118654752f));
        v = acc.z * inv; r.z = 0.5f * v * (1.f + erff(v * 0.70710678118654752f));
        v = acc.w * inv; r.w = 0.5f * v * (1.f + erff(v * 0.70710678118654752f));
        *(float4*)(aggA + (size_t)node * 128 + c) = r;
    }
}

// ---------------- BatchNorm (standalone; both node types per launch) ----------------
__global__ void bn_stats2(const float* __restrict__ hA, const float* __restrict__ hP,
                          float* __restrict__ stats)   // [0:256) author, [256:512) paper
{
    int c = threadIdx.x;
    const int nbAb = (NA + 255) / 256;
    float s = 0.f, s2 = 0.f;
    if ((int)blockIdx.x < nbAb) {
        int r0 = blockIdx.x * 256;
        int r1 = min(NA, r0 + 256);
        for (int r = r0; r < r1; r++) {
            float v = hA[(size_t)r * 128 + c];
            s += v; s2 += v * v;
        }
        atomicAdd(&stats[c], s);
        atomicAdd(&stats[128 + c], s2);
    } else {
        int r0 = (blockIdx.x - nbAb) * 256;
        int r1 = min(NP, r0 + 256);
        for (int r = r0; r < r1; r++) {
            float v = hP[(size_t)r * 128 + c];
            s += v; s2 += v * v;
        }
        atomicAdd(&stats[256 + c], s);
        atomicAdd(&stats[256 + 128 + c], s2);
    }
}

__global__ void bn_apply2(const float* __restrict__ hA, const float* __restrict__ hP,
                          const float* __restrict__ stats,
                          const float* __restrict__ gamma, const float* __restrict__ beta,
                          float* __restrict__ outA, float* __restrict__ outP)
{
    int i = blockIdx.x * blockDim.x + threadIdx.x;
    const int totA = NA * 128;
    const int totP = NP * 128;
    if (i < totA) {
        int c = i & 127;
        float invN = 1.f / (float)NA;
        float mu = stats[c] * invN;
        float var = stats[128 + c] * invN - mu * mu;
        outA[i] = (hA[i] - mu) * rsqrtf(var + BN_EPS) * gamma[c] + beta[c];
    } else {
        int k = i - totA;
        if (k >= totP) return;
        int c = k & 127;
        float invN = 1.f / (float)NP;
        float mu = stats[256 + c] * invN;
        float var = stats[256 + 128 + c] * invN - mu * mu;
        outP[k] = (hP[k] - mu) * rsqrtf(var + BN_EPS) * gamma[c] + beta[c];
    }
}

// ---------------------------------------------------------------
static inline int cdiv(long long a, long long b) { return (int)((a + b - 1) / b); }

extern "C" void kernel_launch(void* const* d_in, const int* in_sizes, int n_in,
                              void* d_out, int out_size)
{
    const float* x_author = (const float*)d_in[0];
    const float* x_paper  = (const float*)d_in[1];
    const int* writes_src = (const int*)d_in[2];
    const int* writes_dst = (const int*)d_in[3];
    const int* rev_src    = (const int*)d_in[4];
    const int* rev_dst    = (const int*)d_in[5];
    const int* cites_src  = (const int*)d_in[6];
    const int* cites_dst  = (const int*)d_in[7];
    const float* linA_W   = (const float*)d_in[8];
    const float* linA_b   = (const float*)d_in[9];
    const float* linP_W   = (const float*)d_in[10];
    const float* linP_b   = (const float*)d_in[11];
    const float* kqv_W    = (const float*)d_in[12];
    const float* kqv_b    = (const float*)d_in[13];
    const float* a_k      = (const float*)d_in[14];
    const float* a_v      = (const float*)d_in[15];
    const float* p_rel    = (const float*)d_in[16];
    const float* out_W    = (const float*)d_in[17];
    const float* out_b    = (const float*)d_in[18];
    const float* skipP    = (const float*)d_in[19];
    const float* bn_gamma = (const float*)d_in[20];
    const float* bn_beta  = (const float*)d_in[21];

    float* base = nullptr;
    cudaGetSymbolAddress((void**)&base, g_scratch);

    float* XA    = base + OFF_XA;
    float* XP    = base + OFF_XP;
    __half* A384 = (__half*)(base + OFF_A384);
    __half* P640 = (__half*)(base + OFF_P640);
    float* AGGA  = base + OFF_AGGA;
    float* AGGP  = base + OFF_AGGP;
    float* TMPA  = base + OFF_TMPA;
    float* TMPP  = base + OFF_TMPP;
    float* WA    = base + OFF_WA;
    float* WP    = base + OFF_WP;
    float* WAB   = base + OFF_WAB;
    float* WPB   = base + OFF_WPB;
    float* STATS = base + OFF_STATS;        // per layer: l*512 ([0:256) author, [256:512) paper)
    int* ibase   = (int*)(base + OFF_INT);
    int* ROWP    = ibase + IOFF_ROWP;
    int* ROWA    = ibase + IOFF_ROWA;
    int* CURP    = ibase + IOFF_CURP;
    int* CURA    = ibase + IOFF_CURA;
    int* SRCP    = ibase + IOFF_SRCP;
    int* SRCA    = ibase + IOFF_SRCA;
    int* BS      = ibase + IOFF_BS;

    const int myA = cdiv(NA, 128);   // 391
    const int myP = cdiv(NP, 128);   // 782

    // -------- CSR build + composite weights (merged launches) --------
    const int nbPb = cdiv(NP, 1024), nbAb = cdiv(NA, 1024);
    cudaMemsetAsync(CURP, 0, (size_t)(NP + NA) * 4, 0);       // CURP and CURA contiguous
    cudaMemsetAsync(STATS, 0, 1024 * 4, 0);                   // both layers' BN stats
    hist3<<<cdiv(EW + EC + ER, 256), 256>>>(writes_dst, cites_dst, rev_dst, CURP, CURA);
    scan_partial2<<<nbPb + nbAb, 256>>>(CURP, ROWP, CURA, ROWA, BS, nbPb);
    scan_small2<<<2, 256>>>(BS, nbPb, nbAb);
    add_off2<<<cdiv(NP + NA, 256), 256>>>(ROWP, CURP, ROWA, CURA, BS, nbPb, nbAb);
    scatter3<<<cdiv(EW + EC + ER, 256), 256>>>(writes_src, writes_dst, cites_src, cites_dst,
                                               rev_src, rev_dst, CURP, CURA, SRCP, SRCA);
    wcomp_all<<<cdiv(WA_TOT + WP_TOT, 256), 256>>>(kqv_W, a_k, a_v, WA, WP);
    bcomp_all<<<cdiv(2 * 384 + 2 * 640, 256), 256>>>(kqv_b, a_k, a_v, WAB, WPB);

    // -------- input projections + relu (merged pair) --------
    gemm2<<<dim3(1, myA + myP), 256>>>(
        x_author, 128, linA_W, 128, linA_b, XA, nullptr, 128, NA, 1, nullptr, nullptr,
        x_paper,  128, linP_W, 128, linP_b, XP, nullptr, 128, NP, 1, nullptr, nullptr,
        myA, 1);

    for (int l = 0; l < 2; l++) {
        // merged Q|K|V projections, fp16 output (merged pair; author gx=3, paper gx=5)
        gemm2<<<dim3(5, myA + myP), 256>>>(
            XA, 128, WA + (size_t)l * 128 * 384, 384, WAB + (size_t)l * 384,
            nullptr, A384, 384, NA, 3, nullptr, nullptr,
            XP, 128, WP + (size_t)l * 128 * 640, 640, WPB + (size_t)l * 640,
            nullptr, P640, 640, NP, 5, nullptr, nullptr,
            myA, 0);

        // fused attention + softmax + aggregation + gelu (single launch, both types)
        attn_agg2<<<cdiv((long long)(NP + NA) * 32, 256), 256>>>(
            A384, P640,
            ROWP, SRCP, p_rel + (size_t)(l * 3 + 0) * NH, p_rel + (size_t)(l * 3 + 2) * NH,
            ROWA, SRCA, p_rel + (size_t)(l * 3 + 1) * NH,
            AGGP, AGGA);

        // output projection + fused sigmoid-skip mix (merged pair)
        gemm2<<<dim3(1, myA + myP), 256>>>(
            AGGA, 128, out_W + (size_t)(l * 2 + 0) * 128 * 128, 128, out_b + (size_t)(l * 2 + 0) * 128,
            TMPA, nullptr, 128, NA, 1, XA, skipP + (l * 2 + 0),
            AGGP, 128, out_W + (size_t)(l * 2 + 1) * 128 * 128, 128, out_b + (size_t)(l * 2 + 1) * 128,
            TMPP, nullptr, 128, NP, 1, XP, skipP + (l * 2 + 1),
            myA, 2);

        // batch norm: stats then apply (per-layer stats region, pre-zeroed)
        float* ST = STATS + (size_t)l * 512;
        bn_stats2<<<cdiv(NA, 256) + cdiv(NP, 256), 128>>>(TMPA, TMPP, ST);
        float* outA = (l == 1) ? (float*)d_out : XA;
        float* outP = (l == 1) ? (float*)d_out + (size_t)NA * 128 : XP;
        bn_apply2<<<cdiv((long long)(NA + NP) * 128, 256), 256>>>(TMPA, TMPP, ST,
                                                                  bn_gamma + (size_t)l * 128,
                                                                  bn_beta + (size_t)l * 128,
                                                                  outA, outP);
    }
}

// round 16
// speedup vs baseline: 1.4411x; 1.4411x over previous
#include <cuda_runtime.h>
#include <cuda_fp16.h>
#include <math.h>
#include <stdint.h>

// ---------------- problem sizes ----------------
#define NA 50000
#define NP 100000
#define HC 128
#define NH 8
#define EW 400000
#define ER 400000
#define EC 800000
#define EP (EW + EC)
#define BN_EPS 1e-5f

// ---------------- scratch layout (float units) ----------------
#define OFF_XA    0ull
#define OFF_XP    (OFF_XA   + (size_t)NA*128)
#define OFF_A384  (OFF_XP   + (size_t)NP*128)        // half[NA*384] : Q | K_rel0 | V_rel0
#define OFF_P640  (OFF_A384 + (size_t)NA*192)        // half[NP*640] : Q | K_rel2 | V_rel2 | K_rel1 | V_rel1
#define OFF_AGGA  (OFF_P640 + (size_t)NP*320)
#define OFF_AGGP  (OFF_AGGA + (size_t)NA*128)
#define OFF_TMPA  (OFF_AGGP + (size_t)NP*128)
#define OFF_TMPP  (OFF_TMPA + (size_t)NA*128)
#define OFF_WA    (OFF_TMPP + (size_t)NP*128)        // 2 * 128 * 384
#define OFF_WP    (OFF_WA   + 2ull*128*384)          // 2 * 128 * 640
#define OFF_WAB   (OFF_WP   + 2ull*128*640)          // 2 * 384
#define OFF_WPB   (OFF_WAB  + 2ull*384)              // 2 * 640
#define OFF_STATS (OFF_WPB  + 2ull*640)              // 2 layers * 512
// integer region
#define OFF_INT   (OFF_STATS + 1024ull)
#define IOFF_ROWP 0ull
#define IOFF_ROWA (IOFF_ROWP + NP + 1)
#define IOFF_CURP (IOFF_ROWA + NA + 1)
#define IOFF_CURA (IOFF_CURP + NP)
#define IOFF_SRCP (IOFF_CURA + NA)
#define IOFF_SRCA (IOFF_SRCP + EP)
#define IOFF_BS   (IOFF_SRCA + ER)
#define INT_TOTAL (IOFF_BS + 256)
#define TOTAL_FLOATS (OFF_INT + INT_TOTAL + 64ull)

__device__ float g_scratch[TOTAL_FLOATS];

// ---------------- tf32 helpers ----------------
__device__ __forceinline__ uint32_t f2tf32(float x)
{
    uint32_t r;
    asm("cvt.rna.tf32.f32 %0, %1;" : "=r"(r) : "f"(x));
    return r;
}

__device__ __forceinline__ void mma_tf32(float4& c, const uint32_t* a, const uint32_t* b)
{
    asm volatile(
        "mma.sync.aligned.m16n8k8.row.col.f32.tf32.tf32.f32 "
        "{%0,%1,%2,%3}, {%4,%5,%6,%7}, {%8,%9}, {%0,%1,%2,%3};"
        : "+f"(c.x), "+f"(c.y), "+f"(c.z), "+f"(c.w)
        : "r"(a[0]), "r"(a[1]), "r"(a[2]), "r"(a[3]), "r"(b[0]), "r"(b[1]));
}

__device__ __forceinline__ float4 ld4h(const __half* p)
{
    __half2 a = *(const __half2*)p;
    __half2 b = *(const __half2*)(p + 2);
    float2 fa = __half22float2(a), fb = __half22float2(b);
    return make_float4(fa.x, fa.y, fb.x, fb.y);
}

// ---------------- dual-problem tf32x2 GEMM (protected; R14 byte-identical) -------
__global__ void __launch_bounds__(256)
gemm2(const float* __restrict__ A0, int lda0, const float* __restrict__ W0, int ldw0,
      const float* __restrict__ b0, float* __restrict__ C0, __half* __restrict__ Ch0,
      int ldc0, int M0, int gx0, const float* __restrict__ x0, const float* __restrict__ s0,
      const float* __restrict__ A1, int lda1, const float* __restrict__ W1, int ldw1,
      const float* __restrict__ b1, float* __restrict__ C1, __half* __restrict__ Ch1,
      int ldc1, int M1, int gx1, const float* __restrict__ x1, const float* __restrict__ s1,
      int gy1, int act)
{
    __shared__ uint32_t As[128][20];
    __shared__ uint32_t Bs[16][136], Bl[16][136];

    const float* A; const float* W; const float* bias; float* C; __half* Ch;
    const float* xold; const float* skipv;
    int lda, ldw, ldc, M, gx, bm;
    if ((int)blockIdx.y < gy1) {
        A = A0; W = W0; bias = b0; C = C0; Ch = Ch0; xold = x0; skipv = s0;
        lda = lda0; ldw = ldw0; ldc = ldc0; M = M0; gx = gx0;
        bm = blockIdx.y * 128;
    } else {
        A = A1; W = W1; bias = b1; C = C1; Ch = Ch1; xold = x1; skipv = s1;
        lda = lda1; ldw = ldw1; ldc = ldc1; M = M1; gx = gx1;
        bm = (blockIdx.y - gy1) * 128;
    }
    if ((int)blockIdx.x >= gx) return;

    const int bn = blockIdx.x * 128;
    const int tid = threadIdx.x;
    const int lane = tid & 31;
    const int warp = tid >> 5;
    const int wm = warp >> 2;
    const int wn = warp & 3;

    float4 acc[4][4];
#pragma unroll
    for (int i = 0; i < 4; i++)
#pragma unroll
        for (int j = 0; j < 4; j++) acc[i][j] = make_float4(0.f, 0.f, 0.f, 0.f);

    for (int k0 = 0; k0 < 128; k0 += 16) {
#pragma unroll
        for (int i = 0; i < 2; i++) {
            int id  = tid + i * 256;
            int row = id >> 2;
            int kc  = (id & 3) * 4;
            int grow = bm + row;
            float4 v = make_float4(0.f, 0.f, 0.f, 0.f);
            if (grow < M) v = *(const float4*)(A + (size_t)grow * lda + k0 + kc);
            As[row][kc + 0] = f2tf32(v.x); As[row][kc + 1] = f2tf32(v.y);
            As[row][kc + 2] = f2tf32(v.z); As[row][kc + 3] = f2tf32(v.w);
        }
#pragma unroll
        for (int i = 0; i < 2; i++) {
            int id  = tid + i * 256;
            int row = id >> 5;
            int col = (id & 31) * 4;
            float4 v = *(const float4*)(W + (size_t)(k0 + row) * ldw + bn + col);
            uint32_t h;
            h = f2tf32(v.x); Bs[row][col + 0] = h; Bl[row][col + 0] = f2tf32(v.x - __uint_as_float(h));
            h = f2tf32(v.y); Bs[row][col + 1] = h; Bl[row][col + 1] = f2tf32(v.y - __uint_as_float(h));
            h = f2tf32(v.z); Bs[row][col + 2] = h; Bl[row][col + 2] = f2tf32(v.z - __uint_as_float(h));
            h = f2tf32(v.w); Bs[row][col + 3] = h; Bl[row][col + 3] = f2tf32(v.w - __uint_as_float(h));
        }
        __syncthreads();

#pragma unroll
        for (int ks = 0; ks < 16; ks += 8) {
            uint32_t af[4][4];
            const int kc = ks + (lane & 3);
#pragma unroll
            for (int mf = 0; mf < 4; mf++) {
                int r = wm * 64 + mf * 16 + (lane >> 2);
                af[mf][0] = As[r][kc];
                af[mf][1] = As[r + 8][kc];
                af[mf][2] = As[r][kc + 4];
                af[mf][3] = As[r + 8][kc + 4];
            }
            uint32_t bh[4][2], bl[4][2];
#pragma unroll
            for (int nf = 0; nf < 4; nf++) {
                int n = wn * 32 + nf * 8 + (lane >> 2);
                bh[nf][0] = Bs[kc][n];     bl[nf][0] = Bl[kc][n];
                bh[nf][1] = Bs[kc + 4][n]; bl[nf][1] = Bl[kc + 4][n];
            }
#pragma unroll
            for (int mf = 0; mf < 4; mf++)
#pragma unroll
                for (int nf = 0; nf < 4; nf++) {
                    mma_tf32(acc[mf][nf], af[mf], bl[nf]);
                    mma_tf32(acc[mf][nf], af[mf], bh[nf]);
                }
        }
        __syncthreads();
    }

    const int lr = lane >> 2;
    const int lc = (lane & 3) * 2;
    float sk = 0.f;
    if (act == 2) sk = 1.f / (1.f + __expf(-skipv[0]));
    float2 bv[4];
#pragma unroll
    for (int nf = 0; nf < 4; nf++) {
        int c0 = bn + wn * 32 + nf * 8 + lc;
        bv[nf] = *(const float2*)(bias + c0);
    }
#pragma unroll
    for (int mf = 0; mf < 4; mf++) {
        int r0 = bm + wm * 64 + mf * 16 + lr;
        int r1 = r0 + 8;
#pragma unroll
        for (int nf = 0; nf < 4; nf++) {
            int c0 = bn + wn * 32 + nf * 8 + lc;
            float4 a = acc[mf][nf];
            float2 o0 = make_float2(a.x + bv[nf].x, a.y + bv[nf].y);
            float2 o1 = make_float2(a.z + bv[nf].x, a.w + bv[nf].y);
            if (act == 1) {
                o0.x = fmaxf(o0.x, 0.f); o0.y = fmaxf(o0.y, 0.f);
                o1.x = fmaxf(o1.x, 0.f); o1.y = fmaxf(o1.y, 0.f);
            } else if (act == 2) {
                if (r0 < M) {
                    float2 xv = *(const float2*)(xold + (size_t)r0 * ldc + c0);
                    o0.x = sk * o0.x + (1.f - sk) * xv.x;
                    o0.y = sk * o0.y + (1.f - sk) * xv.y;
                }
                if (r1 < M) {
                    float2 xv = *(const float2*)(xold + (size_t)r1 * ldc + c0);
                    o1.x = sk * o1.x + (1.f - sk) * xv.x;
                    o1.y = sk * o1.y + (1.f - sk) * xv.y;
                }
            }
            if (Ch) {
                if (r0 < M) *(__half2*)(Ch + (size_t)r0 * ldc + c0) = __floats2half2_rn(o0.x, o0.y);
                if (r1 < M) *(__half2*)(Ch + (size_t)r1 * ldc + c0) = __floats2half2_rn(o1.x, o1.y);
            } else {
                if (r0 < M) *(float2*)(C + (size_t)r0 * ldc + c0) = o0;
                if (r1 < M) *(float2*)(C + (size_t)r1 * ldc + c0) = o1;
            }
        }
    }
}

// ---------------- composite weights: author [128x384], paper [128x640] --------
__global__ void wcompA(const float* __restrict__ kqv_W, const float* __restrict__ a_k,
                       const float* __restrict__ a_v, float* __restrict__ WA)
{
    int gid = blockIdx.x * blockDim.x + threadIdx.x;
    if (gid >= 2 * 128 * 384) return;
    int l = gid / (128 * 384);
    int rem = gid % (128 * 384);
    int r = rem / 384, c = rem % 384;
    const float* Wrow = kqv_W + (size_t)(l * 2 + 0) * 128 * 384 + (size_t)r * 384;
    float s;
    if (c < 128) {
        s = Wrow[128 + c];
    } else {
        int cc = c - 128;
        int c2 = cc & 127, h = c2 >> 4, e = c2 & 15;
        const float* Wb = Wrow + ((cc < 128) ? 0 : 256);
        const float* Am = ((cc < 128) ? a_k : a_v) + (size_t)(l * 3 + 0) * 2048 + h * 256 + e;
        s = 0.f;
#pragma unroll
        for (int dd = 0; dd < 16; dd++) s += Wb[h * 16 + dd] * Am[dd * 16];
    }
    WA[gid] = s;
}

__global__ void wcompP(const float* __restrict__ kqv_W, const float* __restrict__ a_k,
                       const float* __restrict__ a_v, float* __restrict__ WP)
{
    int gid = blockIdx.x * blockDim.x + threadIdx.x;
    if (gid >= 2 * 128 * 640) return;
    int l = gid / (128 * 640);
    int rem = gid % (128 * 640);
    int r = rem / 640, c = rem % 640;
    const float* Wrow = kqv_W + (size_t)(l * 2 + 1) * 128 * 384 + (size_t)r * 384;
    float s;
    if (c < 128) {
        s = Wrow[128 + c];
    } else {
        int rel = (c < 384) ? 2 : 1;
        int cc = (c < 384) ? (c - 128) : (c - 384);
        int c2 = cc & 127, h = c2 >> 4, e = c2 & 15;
        const float* Wb = Wrow + ((cc < 128) ? 0 : 256);
        const float* Am = ((cc < 128) ? a_k : a_v) + (size_t)(l * 3 + rel) * 2048 + h * 256 + e;
        s = 0.f;
#pragma unroll
        for (int dd = 0; dd < 16; dd++) s += Wb[h * 16 + dd] * Am[dd * 16];
    }
    WP[gid] = s;
}

__global__ void bcompA(const float* __restrict__ kqv_b, const float* __restrict__ a_k,
                       const float* __restrict__ a_v, float* __restrict__ WAB)
{
    int gid = blockIdx.x * blockDim.x + threadIdx.x;
    if (gid >= 2 * 384) return;
    int l = gid / 384, c = gid % 384;
    const float* brow = kqv_b + (size_t)(l * 2 + 0) * 384;
    float s;
    if (c < 128) {
        s = brow[128 + c];
    } else {
        int cc = c - 128;
        int c2 = cc & 127, h = c2 >> 4, e = c2 & 15;
        const float* bb = brow + ((cc < 128) ? 0 : 256);
        const float* Am = ((cc < 128) ? a_k : a_v) + (size_t)(l * 3 + 0) * 2048 + h * 256 + e;
        s = 0.f;
#pragma unroll
        for (int dd = 0; dd < 16; dd++) s += bb[h * 16 + dd] * Am[dd * 16];
    }
    WAB[gid] = s;
}

__global__ void bcompP(const float* __restrict__ kqv_b, const float* __restrict__ a_k,
                       const float* __restrict__ a_v, float* __restrict__ WPB)
{
    int gid = blockIdx.x * blockDim.x + threadIdx.x;
    if (gid >= 2 * 640) return;
    int l = gid / 640, c = gid % 640;
    const float* brow = kqv_b + (size_t)(l * 2 + 1) * 384;
    float s;
    if (c < 128) {
        s = brow[128 + c];
    } else {
        int rel = (c < 384) ? 2 : 1;
        int cc = (c < 384) ? (c - 128) : (c - 384);
        int c2 = cc & 127, h = c2 >> 4, e = c2 & 15;
        const float* bb = brow + ((cc < 128) ? 0 : 256);
        const float* Am = ((cc < 128) ? a_k : a_v) + (size_t)(l * 3 + rel) * 2048 + h * 256 + e;
        s = 0.f;
#pragma unroll
        for (int dd = 0; dd < 16; dd++) s += bb[h * 16 + dd] * Am[dd * 16];
    }
    WPB[gid] = s;
}

// ---------------- CSR build (sequential scatter: preserves relation-grouped order) --
__global__ void hist_kernel(const int* __restrict__ dst, int* __restrict__ deg, int E)
{
    int i = blockIdx.x * blockDim.x + threadIdx.x;
    if (i < E) atomicAdd(&deg[dst[i]], 1);
}

__global__ void scan_partial(const int* __restrict__ deg, int* __restrict__ row,
                             int* __restrict__ bsums, int n)
{
    __shared__ int warpsum[8];
    int t = threadIdx.x;
    int lane = t & 31, wid = t >> 5;
    int base = blockIdx.x * 1024 + t * 4;
    int v0 = (base + 0 < n) ? deg[base + 0] : 0;
    int v1 = (base + 1 < n) ? deg[base + 1] : 0;
    int v2 = (base + 2 < n) ? deg[base + 2] : 0;
    int v3 = (base + 3 < n) ? deg[base + 3] : 0;
    int e0 = 0, e1 = v0, e2 = e1 + v1, e3 = e2 + v2;
    int tot = e3 + v3;
    int inc = tot;
#pragma unroll
    for (int off = 1; off < 32; off <<= 1) {
        int y = __shfl_up_sync(0xffffffffu, inc, off);
        if (lane >= off) inc += y;
    }
    if (lane == 31) warpsum[wid] = inc;
    __syncthreads();
    if (wid == 0) {
        int w = (lane < 8) ? warpsum[lane] : 0;
#pragma unroll
        for (int off = 1; off < 8; off <<= 1) {
            int y = __shfl_up_sync(0xffffffffu, w, off);
            if (lane >= off) w += y;
        }
        if (lane < 8) warpsum[lane] = w;
    }
    __syncthreads();
    int warpExcl = (wid == 0) ? 0 : warpsum[wid - 1];
    int thrExcl = warpExcl + inc - tot;
    if (base + 0 < n) row[base + 0] = thrExcl + e0;
    if (base + 1 < n) row[base + 1] = thrExcl + e1;
    if (base + 2 < n) row[base + 2] = thrExcl + e2;
    if (base + 3 < n) row[base + 3] = thrExcl + e3;
    if (t == 0) bsums[blockIdx.x] = warpsum[7];
}

__global__ void scan_small(int* __restrict__ bsums, int nb)
{
    __shared__ int warpsum[8];
    int t = threadIdx.x;
    int lane = t & 31, wid = t >> 5;
    int v = (t < nb) ? bsums[t] : 0;
    int inc = v;
#pragma unroll
    for (int off = 1; off < 32; off <<= 1) {
        int y = __shfl_up_sync(0xffffffffu, inc, off);
        if (lane >= off) inc += y;
    }
    if (lane == 31) warpsum[wid] = inc;
    __syncthreads();
    if (wid == 0) {
        int w = (lane < 8) ? warpsum[lane] : 0;
#pragma unroll
        for (int off = 1; off < 8; off <<= 1) {
            int y = __shfl_up_sync(0xffffffffu, w, off);
            if (lane >= off) w += y;
        }
        if (lane < 8) warpsum[lane] = w;
    }
    __syncthreads();
    int warpExcl = (wid == 0) ? 0 : warpsum[wid - 1];
    int excl = warpExcl + inc - v;
    if (t < nb) bsums[t] = excl;
    if (t == 255) bsums[nb] = warpExcl + inc;
}

__global__ void add_off(int* __restrict__ row, int* __restrict__ cur,
                        const int* __restrict__ bsums, int n, int nb)
{
    int i = blockIdx.x * blockDim.x + threadIdx.x;
    if (i < n) {
        int r = row[i] + bsums[i >> 10];
        row[i] = r;
        cur[i] = r;
    }
    if (i == 0) row[n] = bsums[nb];
}

__global__ void scatter_kernel(const int* __restrict__ src, const int* __restrict__ dst,
                               int* __restrict__ cursor, int* __restrict__ out,
                               int E, int srcOffset)
{
    int i = blockIdx.x * blockDim.x + threadIdx.x;
    if (i >= E) return;
    int p = atomicAdd(&cursor[dst[i]], 1);
    out[p] = src[i] + srcOffset;
}

// ---------------- fused attention (protected; R14 byte-identical) ----
__global__ void attn_agg2(const __half* __restrict__ A384, const __half* __restrict__ P640,
                          const int* __restrict__ rowP, const int* __restrict__ srcP,
                          const float* __restrict__ prel0, const float* __restrict__ prel2,
                          const int* __restrict__ rowA, const int* __restrict__ srcA,
                          const float* __restrict__ prel1,
                          float* __restrict__ aggP, float* __restrict__ aggA)
{
    int gwarp = (blockIdx.x * blockDim.x + threadIdx.x) >> 5;
    int lane = threadIdx.x & 31;
    if (gwarp >= NP + NA) return;
    int h = lane >> 2;
    int c = h * 16 + (lane & 3) * 4;

    float m = -INFINITY, s = 0.f;
    float4 acc = make_float4(0.f, 0.f, 0.f, 0.f);

    if (gwarp < NP) {
        int node = gwarp;
        float4 q4 = ld4h(P640 + (size_t)node * 640 + c);
        float pA = prel0[h] * 0.25f;
        float pB = prel2[h] * 0.25f;
        int js = rowP[node], je = rowP[node + 1];
        int j = js;
        for (; j + 1 < je; j += 2) {
            int sr1 = srcP[j];
            int sr2 = srcP[j + 1];
            const __half* kv1 = (sr1 < NA) ? (A384 + (size_t)sr1 * 384 + 128)
                                           : (P640 + (size_t)(sr1 - NA) * 640 + 128);
            const __half* kv2 = (sr2 < NA) ? (A384 + (size_t)sr2 * 384 + 128)
                                           : (P640 + (size_t)(sr2 - NA) * 640 + 128);
            float4 k1 = ld4h(kv1 + c);
            float4 k2 = ld4h(kv2 + c);
            float p1 = q4.x * k1.x + q4.y * k1.y + q4.z * k1.z + q4.w * k1.w;
            float p2 = q4.x * k2.x + q4.y * k2.y + q4.z * k2.z + q4.w * k2.w;
            p1 += __shfl_xor_sync(0xffffffffu, p1, 1);
            p2 += __shfl_xor_sync(0xffffffffu, p2, 1);
            p1 += __shfl_xor_sync(0xffffffffu, p1, 2);
            p2 += __shfl_xor_sync(0xffffffffu, p2, 2);
            float a1 = p1 * ((sr1 < NA) ? pA : pB);
            float a2 = p2 * ((sr2 < NA) ? pA : pB);
            float4 v1 = ld4h(kv1 + 128 + c);
            float4 v2 = ld4h(kv2 + 128 + c);
            float newm = fmaxf(m, fmaxf(a1, a2));
            float scl = __expf(m - newm);
            float w1 = __expf(a1 - newm);
            float w2 = __expf(a2 - newm);
            s = s * scl + w1 + w2;
            acc.x = acc.x * scl + w1 * v1.x + w2 * v2.x;
            acc.y = acc.y * scl + w1 * v1.y + w2 * v2.y;
            acc.z = acc.z * scl + w1 * v1.z + w2 * v2.z;
            acc.w = acc.w * scl + w1 * v1.w + w2 * v2.w;
            m = newm;
        }
        for (; j < je; j++) {
            int sr = srcP[j];
            const __half* kv = (sr < NA) ? (A384 + (size_t)sr * 384 + 128)
                                         : (P640 + (size_t)(sr - NA) * 640 + 128);
            float4 k1 = ld4h(kv + c);
            float part = q4.x * k1.x + q4.y * k1.y + q4.z * k1.z + q4.w * k1.w;
            part += __shfl_xor_sync(0xffffffffu, part, 1);
            part += __shfl_xor_sync(0xffffffffu, part, 2);
            float a = part * ((sr < NA) ? pA : pB);
            float newm = fmaxf(m, a);
            float scl = __expf(m - newm);
            float w = __expf(a - newm);
            s = s * scl + w;
            float4 v1 = ld4h(kv + 128 + c);
            acc.x = acc.x * scl + w * v1.x;
            acc.y = acc.y * scl + w * v1.y;
            acc.z = acc.z * scl + w * v1.z;
            acc.w = acc.w * scl + w * v1.w;
            m = newm;
        }
        float inv = 1.f / (s + 1e-16f);
        float4 r;
        float v;
        v = acc.x * inv; r.x = 0.5f * v * (1.f + erff(v * 0.70710678118654752f));
        v = acc.y * inv; r.y = 0.5f * v * (1.f + erff(v * 0.70710678118654752f));
        v = acc.z * inv; r.z = 0.5f * v * (1.f + erff(v * 0.70710678118654752f));
        v = acc.w * inv; r.w = 0.5f * v * (1.f + erff(v * 0.70710678118654752f));
        *(float4*)(aggP + (size_t)node * 128 + c) = r;
    } else {
        int node = gwarp - NP;
        float4 q4 = ld4h(A384 + (size_t)node * 384 + c);
        float pr = prel1[h] * 0.25f;
        int js = rowA[node], je = rowA[node + 1];
        int j = js;
        for (; j + 1 < je; j += 2) {
            int s1 = srcA[j];
            int s2 = srcA[j + 1];
            const __half* kv1 = P640 + (size_t)s1 * 640 + 384;
            const __half* kv2 = P640 + (size_t)s2 * 640 + 384;
            float4 k1 = ld4h(kv1 + c);
            float4 k2 = ld4h(kv2 + c);
            float p1 = q4.x * k1.x + q4.y * k1.y + q4.z * k1.z + q4.w * k1.w;
            float p2 = q4.x * k2.x + q4.y * k2.y + q4.z * k2.z + q4.w * k2.w;
            p1 += __shfl_xor_sync(0xffffffffu, p1, 1);
            p2 += __shfl_xor_sync(0xffffffffu, p2, 1);
            p1 += __shfl_xor_sync(0xffffffffu, p1, 2);
            p2 += __shfl_xor_sync(0xffffffffu, p2, 2);
            float a1 = p1 * pr;
            float a2 = p2 * pr;
            float4 v1 = ld4h(kv1 + 128 + c);
            float4 v2 = ld4h(kv2 + 128 + c);
            float newm = fmaxf(m, fmaxf(a1, a2));
            float scl = __expf(m - newm);
            float w1 = __expf(a1 - newm);
            float w2 = __expf(a2 - newm);
            s = s * scl + w1 + w2;
            acc.x = acc.x * scl + w1 * v1.x + w2 * v2.x;
            acc.y = acc.y * scl + w1 * v1.y + w2 * v2.y;
            acc.z = acc.z * scl + w1 * v1.z + w2 * v2.z;
            acc.w = acc.w * scl + w1 * v1.w + w2 * v2.w;
            m = newm;
        }
        for (; j < je; j++) {
            int s1 = srcA[j];
            const __half* kv = P640 + (size_t)s1 * 640 + 384;
            float4 k1 = ld4h(kv + c);
            float part = q4.x * k1.x + q4.y * k1.y + q4.z * k1.z + q4.w * k1.w;
            part += __shfl_xor_sync(0xffffffffu, part, 1);
            part += __shfl_xor_sync(0xffffffffu, part, 2);
            float a = part * pr;
            float newm = fmaxf(m, a);
            float scl = __expf(m - newm);
            float w = __expf(a - newm);
            s = s * scl + w;
            float4 v1 = ld4h(kv + 128 + c);
            acc.x = acc.x * scl + w * v1.x;
            acc.y = acc.y * scl + w * v1.y;
            acc.z = acc.z * scl + w * v1.z;
            acc.w = acc.w * scl + w * v1.w;
            m = newm;
        }
        float inv = 1.f / (s + 1e-16f);
        float4 r;
        float v;
        v = acc.x * inv; r.x = 0.5f * v * (1.f + erff(v * 0.70710678118654752f));
        v = acc.y * inv; r.y = 0.5f * v * (1.f + erff(v * 0.70710678118654752f));
        v = acc.z * inv; r.z = 0.5f * v * (1.f + erff(v * 0.70710678118654752f));
        v = acc.w * inv; r.w = 0.5f * v * (1.f + erff(v * 0.70710678118654752f));
        *(float4*)(aggA + (size_t)node * 128 + c) = r;
    }
}

// ---------------- BatchNorm (standalone; both node types per launch) ----------------
__global__ void bn_stats2(const float* __restrict__ hA, const float* __restrict__ hP,
                          float* __restrict__ stats)   // [0:256) author, [256:512) paper
{
    int c = threadIdx.x;
    const int nbAb = (NA + 255) / 256;
    float s = 0.f, s2 = 0.f;
    if ((int)blockIdx.x < nbAb) {
        int r0 = blockIdx.x * 256;
        int r1 = min(NA, r0 + 256);
        for (int r = r0; r < r1; r++) {
            float v = hA[(size_t)r * 128 + c];
            s += v; s2 += v * v;
        }
        atomicAdd(&stats[c], s);
        atomicAdd(&stats[128 + c], s2);
    } else {
        int r0 = (blockIdx.x - nbAb) * 256;
        int r1 = min(NP, r0 + 256);
        for (int r = r0; r < r1; r++) {
            float v = hP[(size_t)r * 128 + c];
            s += v; s2 += v * v;
        }
        atomicAdd(&stats[256 + c], s);
        atomicAdd(&stats[256 + 128 + c], s2);
    }
}

__global__ void bn_apply2(const float* __restrict__ hA, const float* __restrict__ hP,
                          const float* __restrict__ stats,
                          const float* __restrict__ gamma, const float* __restrict__ beta,
                          float* __restrict__ outA, float* __restrict__ outP)
{
    int i = blockIdx.x * blockDim.x + threadIdx.x;
    const int totA = NA * 128;
    const int totP = NP * 128;
    if (i < totA) {
        int c = i & 127;
        float invN = 1.f / (float)NA;
        float mu = stats[c] * invN;
        float var = stats[128 + c] * invN - mu * mu;
        outA[i] = (hA[i] - mu) * rsqrtf(var + BN_EPS) * gamma[c] + beta[c];
    } else {
        int k = i - totA;
        if (k >= totP) return;
        int c = k & 127;
        float invN = 1.f / (float)NP;
        float mu = stats[256 + c] * invN;
        float var = stats[256 + 128 + c] * invN - mu * mu;
        outP[k] = (hP[k] - mu) * rsqrtf(var + BN_EPS) * gamma[c] + beta[c];
    }
}

// ---------------------------------------------------------------
static inline int cdiv(long long a, long long b) { return (int)((a + b - 1) / b); }

extern "C" void kernel_launch(void* const* d_in, const int* in_sizes, int n_in,
                              void* d_out, int out_size)
{
    const float* x_author = (const float*)d_in[0];
    const float* x_paper  = (const float*)d_in[1];
    const int* writes_src = (const int*)d_in[2];
    const int* writes_dst = (const int*)d_in[3];
    const int* rev_src    = (const int*)d_in[4];
    const int* rev_dst    = (const int*)d_in[5];
    const int* cites_src  = (const int*)d_in[6];
    const int* cites_dst  = (const int*)d_in[7];
    const float* linA_W   = (const float*)d_in[8];
    const float* linA_b   = (const float*)d_in[9];
    const float* linP_W   = (const float*)d_in[10];
    const float* linP_b   = (const float*)d_in[11];
    const float* kqv_W    = (const float*)d_in[12];
    const float* kqv_b    = (const float*)d_in[13];
    const float* a_k      = (const float*)d_in[14];
    const float* a_v      = (const float*)d_in[15];
    const float* p_rel    = (const float*)d_in[16];
    const float* out_W    = (const float*)d_in[17];
    const float* out_b    = (const float*)d_in[18];
    const float* skipP    = (const float*)d_in[19];
    const float* bn_gamma = (const float*)d_in[20];
    const float* bn_beta  = (const float*)d_in[21];

    float* base = nullptr;
    cudaGetSymbolAddress((void**)&base, g_scratch);

    float* XA    = base + OFF_XA;
    float* XP    = base + OFF_XP;
    __half* A384 = (__half*)(base + OFF_A384);
    __half* P640 = (__half*)(base + OFF_P640);
    float* AGGA  = base + OFF_AGGA;
    float* AGGP  = base + OFF_AGGP;
    float* TMPA  = base + OFF_TMPA;
    float* TMPP  = base + OFF_TMPP;
    float* WA    = base + OFF_WA;
    float* WP    = base + OFF_WP;
    float* WAB   = base + OFF_WAB;
    float* WPB   = base + OFF_WPB;
    float* STATS = base + OFF_STATS;        // per layer: l*512 ([0:256) author, [256:512) paper)
    int* ibase   = (int*)(base + OFF_INT);
    int* ROWP    = ibase + IOFF_ROWP;
    int* ROWA    = ibase + IOFF_ROWA;
    int* CURP    = ibase + IOFF_CURP;
    int* CURA    = ibase + IOFF_CURA;
    int* SRCP    = ibase + IOFF_SRCP;
    int* SRCA    = ibase + IOFF_SRCA;
    int* BS      = ibase + IOFF_BS;

    const int myA = cdiv(NA, 128);   // 391
    const int myP = cdiv(NP, 128);   // 782

    // -------- CSR build + composite weights (R14 structure; sequential scatter) ----
    const int nbPb = cdiv(NP, 1024), nbAb = cdiv(NA, 1024);
    cudaMemsetAsync(CURP, 0, (size_t)(NP + NA) * 4, 0);   // CURP,CURA contiguous
    cudaMemsetAsync(STATS, 0, 1024 * 4, 0);               // both layers' BN stats
    hist_kernel<<<cdiv(EW, 256), 256>>>(writes_dst, CURP, EW);
    hist_kernel<<<cdiv(EC, 256), 256>>>(cites_dst, CURP, EC);
    hist_kernel<<<cdiv(ER, 256), 256>>>(rev_dst, CURA, ER);
    scan_partial<<<nbPb, 256>>>(CURP, ROWP, BS, NP);
    scan_small<<<1, 256>>>(BS, nbPb);
    add_off<<<cdiv(NP, 256), 256>>>(ROWP, CURP, BS, NP, nbPb);
    scan_partial<<<nbAb, 256>>>(CURA, ROWA, BS, NA);
    scan_small<<<1, 256>>>(BS, nbAb);
    add_off<<<cdiv(NA, 256), 256>>>(ROWA, CURA, BS, NA, nbAb);
    scatter_kernel<<<cdiv(EW, 256), 256>>>(writes_src, writes_dst, CURP, SRCP, EW, 0);
    scatter_kernel<<<cdiv(EC, 256), 256>>>(cites_src, cites_dst, CURP, SRCP, EC, NA);
    scatter_kernel<<<cdiv(ER, 256), 256>>>(rev_src, rev_dst, CURA, SRCA, ER, 0);
    wcompA<<<cdiv(2 * 128 * 384, 256), 256>>>(kqv_W, a_k, a_v, WA);
    wcompP<<<cdiv(2 * 128 * 640, 256), 256>>>(kqv_W, a_k, a_v, WP);
    bcompA<<<3, 256>>>(kqv_b, a_k, a_v, WAB);
    bcompP<<<5, 256>>>(kqv_b, a_k, a_v, WPB);

    // -------- input projections + relu (merged pair) --------
    gemm2<<<dim3(1, myA + myP), 256>>>(
        x_author, 128, linA_W, 128, linA_b, XA, nullptr, 128, NA, 1, nullptr, nullptr,
        x_paper,  128, linP_W, 128, linP_b, XP, nullptr, 128, NP, 1, nullptr, nullptr,
        myA, 1);

    for (int l = 0; l < 2; l++) {
        // merged Q|K|V projections, fp16 output (merged pair; author gx=3, paper gx=5)
        gemm2<<<dim3(5, myA + myP), 256>>>(
            XA, 128, WA + (size_t)l * 128 * 384, 384, WAB + (size_t)l * 384,
            nullptr, A384, 384, NA, 3, nullptr, nullptr,
            XP, 128, WP + (size_t)l * 128 * 640, 640, WPB + (size_t)l * 640,
            nullptr, P640, 640, NP, 5, nullptr, nullptr,
            myA, 0);

        // fused attention + softmax + aggregation + gelu (single launch, both types)
        attn_agg2<<<cdiv((long long)(NP + NA) * 32, 256), 256>>>(
            A384, P640,
            ROWP, SRCP, p_rel + (size_t)(l * 3 + 0) * NH, p_rel + (size_t)(l * 3 + 2) * NH,
            ROWA, SRCA, p_rel + (size_t)(l * 3 + 1) * NH,
            AGGP, AGGA);

        // output projection + fused sigmoid-skip mix (merged pair)
        gemm2<<<dim3(1, myA + myP), 256>>>(
            AGGA, 128, out_W + (size_t)(l * 2 + 0) * 128 * 128, 128, out_b + (size_t)(l * 2 + 0) * 128,
            TMPA, nullptr, 128, NA, 1, XA, skipP + (l * 2 + 0),
            AGGP, 128, out_W + (size_t)(l * 2 + 1) * 128 * 128, 128, out_b + (size_t)(l * 2 + 1) * 128,
            TMPP, nullptr, 128, NP, 1, XP, skipP + (l * 2 + 1),
            myA, 2);

        // batch norm: stats then apply (per-layer stats region, pre-zeroed)
        float* ST = STATS + (size_t)l * 512;
        bn_stats2<<<cdiv(NA, 256) + cdiv(NP, 256), 128>>>(TMPA, TMPP, ST);
        float* outA = (l == 1) ? (float*)d_out : XA;
        float* outP = (l == 1) ? (float*)d_out + (size_t)NA * 128 : XP;
        bn_apply2<<<cdiv((long long)(NA + NP) * 128, 256), 256>>>(TMPA, TMPP, ST,
                                                                  bn_gamma + (size_t)l * 128,
                                                                  bn_beta + (size_t)l * 128,
                                                                  outA, outP);
    }
}

// round 17
// speedup vs baseline: 1.4915x; 1.0350x over previous
#include <cuda_runtime.h>
#include <cuda_fp16.h>
#include <math.h>
#include <stdint.h>

// ---------------- problem sizes ----------------
#define NA 50000
#define NP 100000
#define HC 128
#define NH 8
#define EW 400000
#define ER 400000
#define EC 800000
#define EP (EW + EC)
#define BN_EPS 1e-5f

// ---------------- scratch layout (float units) ----------------
#define OFF_XA    0ull
#define OFF_XP    (OFF_XA   + (size_t)NA*128)
#define OFF_A384  (OFF_XP   + (size_t)NP*128)        // half[NA*384] : Q | K_rel0 | V_rel0
#define OFF_P640  (OFF_A384 + (size_t)NA*192)        // half[NP*640] : Q | K_rel2 | V_rel2 | K_rel1 | V_rel1
#define OFF_AGGA  (OFF_P640 + (size_t)NP*320)
#define OFF_AGGP  (OFF_AGGA + (size_t)NA*128)
#define OFF_TMPA  (OFF_AGGP + (size_t)NP*128)
#define OFF_TMPP  (OFF_TMPA + (size_t)NA*128)
#define OFF_WA    (OFF_TMPP + (size_t)NP*128)        // 2 * 128 * 384
#define OFF_WP    (OFF_WA   + 2ull*128*384)          // 2 * 128 * 640
#define OFF_WAB   (OFF_WP   + 2ull*128*640)          // 2 * 384
#define OFF_WPB   (OFF_WAB  + 2ull*384)              // 2 * 640
#define OFF_STATS (OFF_WPB  + 2ull*640)              // 2 layers * 512
// integer region
#define OFF_INT   (OFF_STATS + 1024ull)
#define IOFF_ROWP 0ull
#define IOFF_ROWA (IOFF_ROWP + NP + 1)
#define IOFF_CURP (IOFF_ROWA + NA + 1)
#define IOFF_CURA (IOFF_CURP + NP)
#define IOFF_SRCP (IOFF_CURA + NA)
#define IOFF_SRCA (IOFF_SRCP + EP)
#define IOFF_BS   (IOFF_SRCA + ER)
#define INT_TOTAL (IOFF_BS + 256)
#define TOTAL_FLOATS (OFF_INT + INT_TOTAL + 64ull)

__device__ float g_scratch[TOTAL_FLOATS];

// ---------------- tf32 helpers ----------------
__device__ __forceinline__ uint32_t f2tf32(float x)
{
    uint32_t r;
    asm("cvt.rna.tf32.f32 %0, %1;" : "=r"(r) : "f"(x));
    return r;
}

__device__ __forceinline__ void mma_tf32(float4& c, const uint32_t* a, const uint32_t* b)
{
    asm volatile(
        "mma.sync.aligned.m16n8k8.row.col.f32.tf32.tf32.f32 "
        "{%0,%1,%2,%3}, {%4,%5,%6,%7}, {%8,%9}, {%0,%1,%2,%3};"
        : "+f"(c.x), "+f"(c.y), "+f"(c.z), "+f"(c.w)
        : "r"(a[0]), "r"(a[1]), "r"(a[2]), "r"(a[3]), "r"(b[0]), "r"(b[1]));
}

__device__ __forceinline__ float4 ld4h(const __half* p)
{
    __half2 a = *(const __half2*)p;
    __half2 b = *(const __half2*)(p + 2);
    float2 fa = __half22float2(a), fb = __half22float2(b);
    return make_float4(fa.x, fa.y, fb.x, fb.y);
}

// ---------------- dual-problem tf32x2 GEMM (protected; R14 byte-identical) -------
__global__ void __launch_bounds__(256)
gemm2(const float* __restrict__ A0, int lda0, const float* __restrict__ W0, int ldw0,
      const float* __restrict__ b0, float* __restrict__ C0, __half* __restrict__ Ch0,
      int ldc0, int M0, int gx0, const float* __restrict__ x0, const float* __restrict__ s0,
      const float* __restrict__ A1, int lda1, const float* __restrict__ W1, int ldw1,
      const float* __restrict__ b1, float* __restrict__ C1, __half* __restrict__ Ch1,
      int ldc1, int M1, int gx1, const float* __restrict__ x1, const float* __restrict__ s1,
      int gy1, int act)
{
    __shared__ uint32_t As[128][20];
    __shared__ uint32_t Bs[16][136], Bl[16][136];

    const float* A; const float* W; const float* bias; float* C; __half* Ch;
    const float* xold; const float* skipv;
    int lda, ldw, ldc, M, gx, bm;
    if ((int)blockIdx.y < gy1) {
        A = A0; W = W0; bias = b0; C = C0; Ch = Ch0; xold = x0; skipv = s0;
        lda = lda0; ldw = ldw0; ldc = ldc0; M = M0; gx = gx0;
        bm = blockIdx.y * 128;
    } else {
        A = A1; W = W1; bias = b1; C = C1; Ch = Ch1; xold = x1; skipv = s1;
        lda = lda1; ldw = ldw1; ldc = ldc1; M = M1; gx = gx1;
        bm = (blockIdx.y - gy1) * 128;
    }
    if ((int)blockIdx.x >= gx) return;

    const int bn = blockIdx.x * 128;
    const int tid = threadIdx.x;
    const int lane = tid & 31;
    const int warp = tid >> 5;
    const int wm = warp >> 2;
    const int wn = warp & 3;

    float4 acc[4][4];
#pragma unroll
    for (int i = 0; i < 4; i++)
#pragma unroll
        for (int j = 0; j < 4; j++) acc[i][j] = make_float4(0.f, 0.f, 0.f, 0.f);

    for (int k0 = 0; k0 < 128; k0 += 16) {
#pragma unroll
        for (int i = 0; i < 2; i++) {
            int id  = tid + i * 256;
            int row = id >> 2;
            int kc  = (id & 3) * 4;
            int grow = bm + row;
            float4 v = make_float4(0.f, 0.f, 0.f, 0.f);
            if (grow < M) v = *(const float4*)(A + (size_t)grow * lda + k0 + kc);
            As[row][kc + 0] = f2tf32(v.x); As[row][kc + 1] = f2tf32(v.y);
            As[row][kc + 2] = f2tf32(v.z); As[row][kc + 3] = f2tf32(v.w);
        }
#pragma unroll
        for (int i = 0; i < 2; i++) {
            int id  = tid + i * 256;
            int row = id >> 5;
            int col = (id & 31) * 4;
            float4 v = *(const float4*)(W + (size_t)(k0 + row) * ldw + bn + col);
            uint32_t h;
            h = f2tf32(v.x); Bs[row][col + 0] = h; Bl[row][col + 0] = f2tf32(v.x - __uint_as_float(h));
            h = f2tf32(v.y); Bs[row][col + 1] = h; Bl[row][col + 1] = f2tf32(v.y - __uint_as_float(h));
            h = f2tf32(v.z); Bs[row][col + 2] = h; Bl[row][col + 2] = f2tf32(v.z - __uint_as_float(h));
            h = f2tf32(v.w); Bs[row][col + 3] = h; Bl[row][col + 3] = f2tf32(v.w - __uint_as_float(h));
        }
        __syncthreads();

#pragma unroll
        for (int ks = 0; ks < 16; ks += 8) {
            uint32_t af[4][4];
            const int kc = ks + (lane & 3);
#pragma unroll
            for (int mf = 0; mf < 4; mf++) {
                int r = wm * 64 + mf * 16 + (lane >> 2);
                af[mf][0] = As[r][kc];
                af[mf][1] = As[r + 8][kc];
                af[mf][2] = As[r][kc + 4];
                af[mf][3] = As[r + 8][kc + 4];
            }
            uint32_t bh[4][2], bl[4][2];
#pragma unroll
            for (int nf = 0; nf < 4; nf++) {
                int n = wn * 32 + nf * 8 + (lane >> 2);
                bh[nf][0] = Bs[kc][n];     bl[nf][0] = Bl[kc][n];
                bh[nf][1] = Bs[kc + 4][n]; bl[nf][1] = Bl[kc + 4][n];
            }
#pragma unroll
            for (int mf = 0; mf < 4; mf++)
#pragma unroll
                for (int nf = 0; nf < 4; nf++) {
                    mma_tf32(acc[mf][nf], af[mf], bl[nf]);
                    mma_tf32(acc[mf][nf], af[mf], bh[nf]);
                }
        }
        __syncthreads();
    }

    const int lr = lane >> 2;
    const int lc = (lane & 3) * 2;
    float sk = 0.f;
    if (act == 2) sk = 1.f / (1.f + __expf(-skipv[0]));
    float2 bv[4];
#pragma unroll
    for (int nf = 0; nf < 4; nf++) {
        int c0 = bn + wn * 32 + nf * 8 + lc;
        bv[nf] = *(const float2*)(bias + c0);
    }
#pragma unroll
    for (int mf = 0; mf < 4; mf++) {
        int r0 = bm + wm * 64 + mf * 16 + lr;
        int r1 = r0 + 8;
#pragma unroll
        for (int nf = 0; nf < 4; nf++) {
            int c0 = bn + wn * 32 + nf * 8 + lc;
            float4 a = acc[mf][nf];
            float2 o0 = make_float2(a.x + bv[nf].x, a.y + bv[nf].y);
            float2 o1 = make_float2(a.z + bv[nf].x, a.w + bv[nf].y);
            if (act == 1) {
                o0.x = fmaxf(o0.x, 0.f); o0.y = fmaxf(o0.y, 0.f);
                o1.x = fmaxf(o1.x, 0.f); o1.y = fmaxf(o1.y, 0.f);
            } else if (act == 2) {
                if (r0 < M) {
                    float2 xv = *(const float2*)(xold + (size_t)r0 * ldc + c0);
                    o0.x = sk * o0.x + (1.f - sk) * xv.x;
                    o0.y = sk * o0.y + (1.f - sk) * xv.y;
                }
                if (r1 < M) {
                    float2 xv = *(const float2*)(xold + (size_t)r1 * ldc + c0);
                    o1.x = sk * o1.x + (1.f - sk) * xv.x;
                    o1.y = sk * o1.y + (1.f - sk) * xv.y;
                }
            }
            if (Ch) {
                if (r0 < M) *(__half2*)(Ch + (size_t)r0 * ldc + c0) = __floats2half2_rn(o0.x, o0.y);
                if (r1 < M) *(__half2*)(Ch + (size_t)r1 * ldc + c0) = __floats2half2_rn(o1.x, o1.y);
            } else {
                if (r0 < M) *(float2*)(C + (size_t)r0 * ldc + c0) = o0;
                if (r1 < M) *(float2*)(C + (size_t)r1 * ldc + c0) = o1;
            }
        }
    }
}

// ---------------- composite weights: author [128x384], paper [128x640] --------
__global__ void wcompA(const float* __restrict__ kqv_W, const float* __restrict__ a_k,
                       const float* __restrict__ a_v, float* __restrict__ WA)
{
    int gid = blockIdx.x * blockDim.x + threadIdx.x;
    if (gid >= 2 * 128 * 384) return;
    int l = gid / (128 * 384);
    int rem = gid % (128 * 384);
    int r = rem / 384, c = rem % 384;
    const float* Wrow = kqv_W + (size_t)(l * 2 + 0) * 128 * 384 + (size_t)r * 384;
    float s;
    if (c < 128) {
        s = Wrow[128 + c];
    } else {
        int cc = c - 128;
        int c2 = cc & 127, h = c2 >> 4, e = c2 & 15;
        const float* Wb = Wrow + ((cc < 128) ? 0 : 256);
        const float* Am = ((cc < 128) ? a_k : a_v) + (size_t)(l * 3 + 0) * 2048 + h * 256 + e;
        s = 0.f;
#pragma unroll
        for (int dd = 0; dd < 16; dd++) s += Wb[h * 16 + dd] * Am[dd * 16];
    }
    WA[gid] = s;
}

__global__ void wcompP(const float* __restrict__ kqv_W, const float* __restrict__ a_k,
                       const float* __restrict__ a_v, float* __restrict__ WP)
{
    int gid = blockIdx.x * blockDim.x + threadIdx.x;
    if (gid >= 2 * 128 * 640) return;
    int l = gid / (128 * 640);
    int rem = gid % (128 * 640);
    int r = rem / 640, c = rem % 640;
    const float* Wrow = kqv_W + (size_t)(l * 2 + 1) * 128 * 384 + (size_t)r * 384;
    float s;
    if (c < 128) {
        s = Wrow[128 + c];
    } else {
        int rel = (c < 384) ? 2 : 1;
        int cc = (c < 384) ? (c - 128) : (c - 384);
        int c2 = cc & 127, h = c2 >> 4, e = c2 & 15;
        const float* Wb = Wrow + ((cc < 128) ? 0 : 256);
        const float* Am = ((cc < 128) ? a_k : a_v) + (size_t)(l * 3 + rel) * 2048 + h * 256 + e;
        s = 0.f;
#pragma unroll
        for (int dd = 0; dd < 16; dd++) s += Wb[h * 16 + dd] * Am[dd * 16];
    }
    WP[gid] = s;
}

__global__ void bcompA(const float* __restrict__ kqv_b, const float* __restrict__ a_k,
                       const float* __restrict__ a_v, float* __restrict__ WAB)
{
    int gid = blockIdx.x * blockDim.x + threadIdx.x;
    if (gid >= 2 * 384) return;
    int l = gid / 384, c = gid % 384;
    const float* brow = kqv_b + (size_t)(l * 2 + 0) * 384;
    float s;
    if (c < 128) {
        s = brow[128 + c];
    } else {
        int cc = c - 128;
        int c2 = cc & 127, h = c2 >> 4, e = c2 & 15;
        const float* bb = brow + ((cc < 128) ? 0 : 256);
        const float* Am = ((cc < 128) ? a_k : a_v) + (size_t)(l * 3 + 0) * 2048 + h * 256 + e;
        s = 0.f;
#pragma unroll
        for (int dd = 0; dd < 16; dd++) s += bb[h * 16 + dd] * Am[dd * 16];
    }
    WAB[gid] = s;
}

__global__ void bcompP(const float* __restrict__ kqv_b, const float* __restrict__ a_k,
                       const float* __restrict__ a_v, float* __restrict__ WPB)
{
    int gid = blockIdx.x * blockDim.x + threadIdx.x;
    if (gid >= 2 * 640) return;
    int l = gid / 640, c = gid % 640;
    const float* brow = kqv_b + (size_t)(l * 2 + 1) * 384;
    float s;
    if (c < 128) {
        s = brow[128 + c];
    } else {
        int rel = (c < 384) ? 2 : 1;
        int cc = (c < 384) ? (c - 128) : (c - 384);
        int c2 = cc & 127, h = c2 >> 4, e = c2 & 15;
        const float* bb = brow + ((cc < 128) ? 0 : 256);
        const float* Am = ((cc < 128) ? a_k : a_v) + (size_t)(l * 3 + rel) * 2048 + h * 256 + e;
        s = 0.f;
#pragma unroll
        for (int dd = 0; dd < 16; dd++) s += bb[h * 16 + dd] * Am[dd * 16];
    }
    WPB[gid] = s;
}

// ---------------- CSR build (sequential scatter: preserves relation-grouped order) --
__global__ void hist_kernel(const int* __restrict__ dst, int* __restrict__ deg, int E)
{
    int i = blockIdx.x * blockDim.x + threadIdx.x;
    if (i < E) atomicAdd(&deg[dst[i]], 1);
}

__global__ void scan_partial(const int* __restrict__ deg, int* __restrict__ row,
                             int* __restrict__ bsums, int n)
{
    __shared__ int warpsum[8];
    int t = threadIdx.x;
    int lane = t & 31, wid = t >> 5;
    int base = blockIdx.x * 1024 + t * 4;
    int v0 = (base + 0 < n) ? deg[base + 0] : 0;
    int v1 = (base + 1 < n) ? deg[base + 1] : 0;
    int v2 = (base + 2 < n) ? deg[base + 2] : 0;
    int v3 = (base + 3 < n) ? deg[base + 3] : 0;
    int e0 = 0, e1 = v0, e2 = e1 + v1, e3 = e2 + v2;
    int tot = e3 + v3;
    int inc = tot;
#pragma unroll
    for (int off = 1; off < 32; off <<= 1) {
        int y = __shfl_up_sync(0xffffffffu, inc, off);
        if (lane >= off) inc += y;
    }
    if (lane == 31) warpsum[wid] = inc;
    __syncthreads();
    if (wid == 0) {
        int w = (lane < 8) ? warpsum[lane] : 0;
#pragma unroll
        for (int off = 1; off < 8; off <<= 1) {
            int y = __shfl_up_sync(0xffffffffu, w, off);
            if (lane >= off) w += y;
        }
        if (lane < 8) warpsum[lane] = w;
    }
    __syncthreads();
    int warpExcl = (wid == 0) ? 0 : warpsum[wid - 1];
    int thrExcl = warpExcl + inc - tot;
    if (base + 0 < n) row[base + 0] = thrExcl + e0;
    if (base + 1 < n) row[base + 1] = thrExcl + e1;
    if (base + 2 < n) row[base + 2] = thrExcl + e2;
    if (base + 3 < n) row[base + 3] = thrExcl + e3;
    if (t == 0) bsums[blockIdx.x] = warpsum[7];
}

__global__ void scan_small(int* __restrict__ bsums, int nb)
{
    __shared__ int warpsum[8];
    int t = threadIdx.x;
    int lane = t & 31, wid = t >> 5;
    int v = (t < nb) ? bsums[t] : 0;
    int inc = v;
#pragma unroll
    for (int off = 1; off < 32; off <<= 1) {
        int y = __shfl_up_sync(0xffffffffu, inc, off);
        if (lane >= off) inc += y;
    }
    if (lane == 31) warpsum[wid] = inc;
    __syncthreads();
    if (wid == 0) {
        int w = (lane < 8) ? warpsum[lane] : 0;
#pragma unroll
        for (int off = 1; off < 8; off <<= 1) {
            int y = __shfl_up_sync(0xffffffffu, w, off);
            if (lane >= off) w += y;
        }
        if (lane < 8) warpsum[lane] = w;
    }
    __syncthreads();
    int warpExcl = (wid == 0) ? 0 : warpsum[wid - 1];
    int excl = warpExcl + inc - v;
    if (t < nb) bsums[t] = excl;
    if (t == 255) bsums[nb] = warpExcl + inc;
}

__global__ void add_off(int* __restrict__ row, int* __restrict__ cur,
                        const int* __restrict__ bsums, int n, int nb)
{
    int i = blockIdx.x * blockDim.x + threadIdx.x;
    if (i < n) {
        int r = row[i] + bsums[i >> 10];
        row[i] = r;
        cur[i] = r;
    }
    if (i == 0) row[n] = bsums[nb];
}

__global__ void scatter_kernel(const int* __restrict__ src, const int* __restrict__ dst,
                               int* __restrict__ cursor, int* __restrict__ out,
                               int E, int srcOffset)
{
    int i = blockIdx.x * blockDim.x + threadIdx.x;
    if (i >= E) return;
    int p = atomicAdd(&cursor[dst[i]], 1);
    out[p] = src[i] + srcOffset;
}

// ---------------- fused attention (4-edge unrolled online softmax) ----
__global__ void attn_agg2(const __half* __restrict__ A384, const __half* __restrict__ P640,
                          const int* __restrict__ rowP, const int* __restrict__ srcP,
                          const float* __restrict__ prel0, const float* __restrict__ prel2,
                          const int* __restrict__ rowA, const int* __restrict__ srcA,
                          const float* __restrict__ prel1,
                          float* __restrict__ aggP, float* __restrict__ aggA)
{
    int gwarp = (blockIdx.x * blockDim.x + threadIdx.x) >> 5;
    int lane = threadIdx.x & 31;
    if (gwarp >= NP + NA) return;
    int h = lane >> 2;
    int c = h * 16 + (lane & 3) * 4;

    float m = -INFINITY, s = 0.f;
    float4 acc = make_float4(0.f, 0.f, 0.f, 0.f);

    if (gwarp < NP) {
        int node = gwarp;
        float4 q4 = ld4h(P640 + (size_t)node * 640 + c);
        float pA = prel0[h] * 0.25f;
        float pB = prel2[h] * 0.25f;
        int js = rowP[node], je = rowP[node + 1];
        int j = js;
        for (; j + 3 < je; j += 4) {
            int sr1 = srcP[j], sr2 = srcP[j + 1], sr3 = srcP[j + 2], sr4 = srcP[j + 3];
            const __half* kv1 = (sr1 < NA) ? (A384 + (size_t)sr1 * 384 + 128)
                                           : (P640 + (size_t)(sr1 - NA) * 640 + 128);
            const __half* kv2 = (sr2 < NA) ? (A384 + (size_t)sr2 * 384 + 128)
                                           : (P640 + (size_t)(sr2 - NA) * 640 + 128);
            const __half* kv3 = (sr3 < NA) ? (A384 + (size_t)sr3 * 384 + 128)
                                           : (P640 + (size_t)(sr3 - NA) * 640 + 128);
            const __half* kv4 = (sr4 < NA) ? (A384 + (size_t)sr4 * 384 + 128)
                                           : (P640 + (size_t)(sr4 - NA) * 640 + 128);
            float4 k1 = ld4h(kv1 + c);
            float4 k2 = ld4h(kv2 + c);
            float4 k3 = ld4h(kv3 + c);
            float4 k4 = ld4h(kv4 + c);
            float p1 = q4.x * k1.x + q4.y * k1.y + q4.z * k1.z + q4.w * k1.w;
            float p2 = q4.x * k2.x + q4.y * k2.y + q4.z * k2.z + q4.w * k2.w;
            float p3 = q4.x * k3.x + q4.y * k3.y + q4.z * k3.z + q4.w * k3.w;
            float p4 = q4.x * k4.x + q4.y * k4.y + q4.z * k4.z + q4.w * k4.w;
            p1 += __shfl_xor_sync(0xffffffffu, p1, 1);
            p2 += __shfl_xor_sync(0xffffffffu, p2, 1);
            p3 += __shfl_xor_sync(0xffffffffu, p3, 1);
            p4 += __shfl_xor_sync(0xffffffffu, p4, 1);
            p1 += __shfl_xor_sync(0xffffffffu, p1, 2);
            p2 += __shfl_xor_sync(0xffffffffu, p2, 2);
            p3 += __shfl_xor_sync(0xffffffffu, p3, 2);
            p4 += __shfl_xor_sync(0xffffffffu, p4, 2);
            float a1 = p1 * ((sr1 < NA) ? pA : pB);
            float a2 = p2 * ((sr2 < NA) ? pA : pB);
            float a3 = p3 * ((sr3 < NA) ? pA : pB);
            float a4 = p4 * ((sr4 < NA) ? pA : pB);
            float4 v1 = ld4h(kv1 + 128 + c);
            float4 v2 = ld4h(kv2 + 128 + c);
            float4 v3 = ld4h(kv3 + 128 + c);
            float4 v4 = ld4h(kv4 + 128 + c);
            float newm = fmaxf(fmaxf(fmaxf(a1, a2), fmaxf(a3, a4)), m);
            float scl = __expf(m - newm);
            float w1 = __expf(a1 - newm);
            float w2 = __expf(a2 - newm);
            float w3 = __expf(a3 - newm);
            float w4 = __expf(a4 - newm);
            s = s * scl + (w1 + w2) + (w3 + w4);
            acc.x = acc.x * scl + (w1 * v1.x + w2 * v2.x) + (w3 * v3.x + w4 * v4.x);
            acc.y = acc.y * scl + (w1 * v1.y + w2 * v2.y) + (w3 * v3.y + w4 * v4.y);
            acc.z = acc.z * scl + (w1 * v1.z + w2 * v2.z) + (w3 * v3.z + w4 * v4.z);
            acc.w = acc.w * scl + (w1 * v1.w + w2 * v2.w) + (w3 * v3.w + w4 * v4.w);
            m = newm;
        }
        for (; j < je; j++) {
            int sr = srcP[j];
            const __half* kv = (sr < NA) ? (A384 + (size_t)sr * 384 + 128)
                                         : (P640 + (size_t)(sr - NA) * 640 + 128);
            float4 k1 = ld4h(kv + c);
            float part = q4.x * k1.x + q4.y * k1.y + q4.z * k1.z + q4.w * k1.w;
            part += __shfl_xor_sync(0xffffffffu, part, 1);
            part += __shfl_xor_sync(0xffffffffu, part, 2);
            float a = part * ((sr < NA) ? pA : pB);
            float newm = fmaxf(m, a);
            float scl = __expf(m - newm);
            float w = __expf(a - newm);
            s = s * scl + w;
            float4 v1 = ld4h(kv + 128 + c);
            acc.x = acc.x * scl + w * v1.x;
            acc.y = acc.y * scl + w * v1.y;
            acc.z = acc.z * scl + w * v1.z;
            acc.w = acc.w * scl + w * v1.w;
            m = newm;
        }
        float inv = 1.f / (s + 1e-16f);
        float4 r;
        float v;
        v = acc.x * inv; r.x = 0.5f * v * (1.f + erff(v * 0.70710678118654752f));
        v = acc.y * inv; r.y = 0.5f * v * (1.f + erff(v * 0.70710678118654752f));
        v = acc.z * inv; r.z = 0.5f * v * (1.f + erff(v * 0.70710678118654752f));
        v = acc.w * inv; r.w = 0.5f * v * (1.f + erff(v * 0.70710678118654752f));
        *(float4*)(aggP + (size_t)node * 128 + c) = r;
    } else {
        int node = gwarp - NP;
        float4 q4 = ld4h(A384 + (size_t)node * 384 + c);
        float pr = prel1[h] * 0.25f;
        int js = rowA[node], je = rowA[node + 1];
        int j = js;
        for (; j + 3 < je; j += 4) {
            int s1 = srcA[j], s2 = srcA[j + 1], s3 = srcA[j + 2], s4 = srcA[j + 3];
            const __half* kv1 = P640 + (size_t)s1 * 640 + 384;
            const __half* kv2 = P640 + (size_t)s2 * 640 + 384;
            const __half* kv3 = P640 + (size_t)s3 * 640 + 384;
            const __half* kv4 = P640 + (size_t)s4 * 640 + 384;
            float4 k1 = ld4h(kv1 + c);
            float4 k2 = ld4h(kv2 + c);
            float4 k3 = ld4h(kv3 + c);
            float4 k4 = ld4h(kv4 + c);
            float p1 = q4.x * k1.x + q4.y * k1.y + q4.z * k1.z + q4.w * k1.w;
            float p2 = q4.x * k2.x + q4.y * k2.y + q4.z * k2.z + q4.w * k2.w;
            float p3 = q4.x * k3.x + q4.y * k3.y + q4.z * k3.z + q4.w * k3.w;
            float p4 = q4.x * k4.x + q4.y * k4.y + q4.z * k4.z + q4.w * k4.w;
            p1 += __shfl_xor_sync(0xffffffffu, p1, 1);
            p2 += __shfl_xor_sync(0xffffffffu, p2, 1);
            p3 += __shfl_xor_sync(0xffffffffu, p3, 1);
            p4 += __shfl_xor_sync(0xffffffffu, p4, 1);
            p1 += __shfl_xor_sync(0xffffffffu, p1, 2);
            p2 += __shfl_xor_sync(0xffffffffu, p2, 2);
            p3 += __shfl_xor_sync(0xffffffffu, p3, 2);
            p4 += __shfl_xor_sync(0xffffffffu, p4, 2);
            float a1 = p1 * pr;
            float a2 = p2 * pr;
            float a3 = p3 * pr;
            float a4 = p4 * pr;
            float4 v1 = ld4h(kv1 + 128 + c);
            float4 v2 = ld4h(kv2 + 128 + c);
            float4 v3 = ld4h(kv3 + 128 + c);
            float4 v4 = ld4h(kv4 + 128 + c);
            float newm = fmaxf(fmaxf(fmaxf(a1, a2), fmaxf(a3, a4)), m);
            float scl = __expf(m - newm);
            float w1 = __expf(a1 - newm);
            float w2 = __expf(a2 - newm);
            float w3 = __expf(a3 - newm);
            float w4 = __expf(a4 - newm);
            s = s * scl + (w1 + w2) + (w3 + w4);
            acc.x = acc.x * scl + (w1 * v1.x + w2 * v2.x) + (w3 * v3.x + w4 * v4.x);
            acc.y = acc.y * scl + (w1 * v1.y + w2 * v2.y) + (w3 * v3.y + w4 * v4.y);
            acc.z = acc.z * scl + (w1 * v1.z + w2 * v2.z) + (w3 * v3.z + w4 * v4.z);
            acc.w = acc.w * scl + (w1 * v1.w + w2 * v2.w) + (w3 * v3.w + w4 * v4.w);
            m = newm;
        }
        for (; j < je; j++) {
            int s1 = srcA[j];
            const __half* kv = P640 + (size_t)s1 * 640 + 384;
            float4 k1 = ld4h(kv + c);
            float part = q4.x * k1.x + q4.y * k1.y + q4.z * k1.z + q4.w * k1.w;
            part += __shfl_xor_sync(0xffffffffu, part, 1);
            part += __shfl_xor_sync(0xffffffffu, part, 2);
            float a = part * pr;
            float newm = fmaxf(m, a);
            float scl = __expf(m - newm);
            float w = __expf(a - newm);
            s = s * scl + w;
            float4 v1 = ld4h(kv + 128 + c);
            acc.x = acc.x * scl + w * v1.x;
            acc.y = acc.y * scl + w * v1.y;
            acc.z = acc.z * scl + w * v1.z;
            acc.w = acc.w * scl + w * v1.w;
            m = newm;
        }
        float inv = 1.f / (s + 1e-16f);
        float4 r;
        float v;
        v = acc.x * inv; r.x = 0.5f * v * (1.f + erff(v * 0.70710678118654752f));
        v = acc.y * inv; r.y = 0.5f * v * (1.f + erff(v * 0.70710678118654752f));
        v = acc.z * inv; r.z = 0.5f * v * (1.f + erff(v * 0.70710678118654752f));
        v = acc.w * inv; r.w = 0.5f * v * (1.f + erff(v * 0.70710678118654752f));
        *(float4*)(aggA + (size_t)node * 128 + c) = r;
    }
}

// ---------------- BatchNorm (standalone; both node types per launch) ----------------
__global__ void bn_stats2(const float* __restrict__ hA, const float* __restrict__ hP,
                          float* __restrict__ stats)   // [0:256) author, [256:512) paper
{
    int c = threadIdx.x;
    const int nbAb = (NA + 255) / 256;
    float s = 0.f, s2 = 0.f;
    if ((int)blockIdx.x < nbAb) {
        int r0 = blockIdx.x * 256;
        int r1 = min(NA, r0 + 256);
        for (int r = r0; r < r1; r++) {
            float v = hA[(size_t)r * 128 + c];
            s += v; s2 += v * v;
        }
        atomicAdd(&stats[c], s);
        atomicAdd(&stats[128 + c], s2);
    } else {
        int r0 = (blockIdx.x - nbAb) * 256;
        int r1 = min(NP, r0 + 256);
        for (int r = r0; r < r1; r++) {
            float v = hP[(size_t)r * 128 + c];
            s += v; s2 += v * v;
        }
        atomicAdd(&stats[256 + c], s);
        atomicAdd(&stats[256 + 128 + c], s2);
    }
}

__global__ void bn_apply2(const float* __restrict__ hA, const float* __restrict__ hP,
                          const float* __restrict__ stats,
                          const float* __restrict__ gamma, const float* __restrict__ beta,
                          float* __restrict__ outA, float* __restrict__ outP)
{
    int i = blockIdx.x * blockDim.x + threadIdx.x;
    const int totA = NA * 128;
    const int totP = NP * 128;
    if (i < totA) {
        int c = i & 127;
        float invN = 1.f / (float)NA;
        float mu = stats[c] * invN;
        float var = stats[128 + c] * invN - mu * mu;
        outA[i] = (hA[i] - mu) * rsqrtf(var + BN_EPS) * gamma[c] + beta[c];
    } else {
        int k = i - totA;
        if (k >= totP) return;
        int c = k & 127;
        float invN = 1.f / (float)NP;
        float mu = stats[256 + c] * invN;
        float var = stats[256 + 128 + c] * invN - mu * mu;
        outP[k] = (hP[k] - mu) * rsqrtf(var + BN_EPS) * gamma[c] + beta[c];
    }
}

// ---------------------------------------------------------------
static inline int cdiv(long long a, long long b) { return (int)((a + b - 1) / b); }

extern "C" void kernel_launch(void* const* d_in, const int* in_sizes, int n_in,
                              void* d_out, int out_size)
{
    const float* x_author = (const float*)d_in[0];
    const float* x_paper  = (const float*)d_in[1];
    const int* writes_src = (const int*)d_in[2];
    const int* writes_dst = (const int*)d_in[3];
    const int* rev_src    = (const int*)d_in[4];
    const int* rev_dst    = (const int*)d_in[5];
    const int* cites_src  = (const int*)d_in[6];
    const int* cites_dst  = (const int*)d_in[7];
    const float* linA_W   = (const float*)d_in[8];
    const float* linA_b   = (const float*)d_in[9];
    const float* linP_W   = (const float*)d_in[10];
    const float* linP_b   = (const float*)d_in[11];
    const float* kqv_W    = (const float*)d_in[12];
    const float* kqv_b    = (const float*)d_in[13];
    const float* a_k      = (const float*)d_in[14];
    const float* a_v      = (const float*)d_in[15];
    const float* p_rel    = (const float*)d_in[16];
    const float* out_W    = (const float*)d_in[17];
    const float* out_b    = (const float*)d_in[18];
    const float* skipP    = (const float*)d_in[19];
    const float* bn_gamma = (const float*)d_in[20];
    const float* bn_beta  = (const float*)d_in[21];

    float* base = nullptr;
    cudaGetSymbolAddress((void**)&base, g_scratch);

    float* XA    = base + OFF_XA;
    float* XP    = base + OFF_XP;
    __half* A384 = (__half*)(base + OFF_A384);
    __half* P640 = (__half*)(base + OFF_P640);
    float* AGGA  = base + OFF_AGGA;
    float* AGGP  = base + OFF_AGGP;
    float* TMPA  = base + OFF_TMPA;
    float* TMPP  = base + OFF_TMPP;
    float* WA    = base + OFF_WA;
    float* WP    = base + OFF_WP;
    float* WAB   = base + OFF_WAB;
    float* WPB   = base + OFF_WPB;
    float* STATS = base + OFF_STATS;
    int* ibase   = (int*)(base + OFF_INT);
    int* ROWP    = ibase + IOFF_ROWP;
    int* ROWA    = ibase + IOFF_ROWA;
    int* CURP    = ibase + IOFF_CURP;
    int* CURA    = ibase + IOFF_CURA;
    int* SRCP    = ibase + IOFF_SRCP;
    int* SRCA    = ibase + IOFF_SRCA;
    int* BS      = ibase + IOFF_BS;

    const int myA = cdiv(NA, 128);   // 391
    const int myP = cdiv(NP, 128);   // 782

    // -------- CSR build + composite weights (sequential scatter preserved) ----
    const int nbPb = cdiv(NP, 1024), nbAb = cdiv(NA, 1024);
    cudaMemsetAsync(CURP, 0, (size_t)(NP + NA) * 4, 0);
    cudaMemsetAsync(STATS, 0, 1024 * 4, 0);
    hist_kernel<<<cdiv(EW, 256), 256>>>(writes_dst, CURP, EW);
    hist_kernel<<<cdiv(EC, 256), 256>>>(cites_dst, CURP, EC);
    hist_kernel<<<cdiv(ER, 256), 256>>>(rev_dst, CURA, ER);
    scan_partial<<<nbPb, 256>>>(CURP, ROWP, BS, NP);
    scan_small<<<1, 256>>>(BS, nbPb);
    add_off<<<cdiv(NP, 256), 256>>>(ROWP, CURP, BS, NP, nbPb);
    scan_partial<<<nbAb, 256>>>(CURA, ROWA, BS, NA);
    scan_small<<<1, 256>>>(BS, nbAb);
    add_off<<<cdiv(NA, 256), 256>>>(ROWA, CURA, BS, NA, nbAb);
    scatter_kernel<<<cdiv(EW, 256), 256>>>(writes_src, writes_dst, CURP, SRCP, EW, 0);
    scatter_kernel<<<cdiv(EC, 256), 256>>>(cites_src, cites_dst, CURP, SRCP, EC, NA);
    scatter_kernel<<<cdiv(ER, 256), 256>>>(rev_src, rev_dst, CURA, SRCA, ER, 0);
    wcompA<<<cdiv(2 * 128 * 384, 256), 256>>>(kqv_W, a_k, a_v, WA);
    wcompP<<<cdiv(2 * 128 * 640, 256), 256>>>(kqv_W, a_k, a_v, WP);
    bcompA<<<3, 256>>>(kqv_b, a_k, a_v, WAB);
    bcompP<<<5, 256>>>(kqv_b, a_k, a_v, WPB);

    // -------- input projections + relu (merged pair) --------
    gemm2<<<dim3(1, myA + myP), 256>>>(
        x_author, 128, linA_W, 128, linA_b, XA, nullptr, 128, NA, 1, nullptr, nullptr,
        x_paper,  128, linP_W, 128, linP_b, XP, nullptr, 128, NP, 1, nullptr, nullptr,
        myA, 1);

    for (int l = 0; l < 2; l++) {
        // merged Q|K|V projections, fp16 output (merged pair)
        gemm2<<<dim3(5, myA + myP), 256>>>(
            XA, 128, WA + (size_t)l * 128 * 384, 384, WAB + (size_t)l * 384,
            nullptr, A384, 384, NA, 3, nullptr, nullptr,
            XP, 128, WP + (size_t)l * 128 * 640, 640, WPB + (size_t)l * 640,
            nullptr, P640, 640, NP, 5, nullptr, nullptr,
            myA, 0);

        // fused attention + softmax + aggregation + gelu (4-edge unrolled)
        attn_agg2<<<cdiv((long long)(NP + NA) * 32, 256), 256>>>(
            A384, P640,
            ROWP, SRCP, p_rel + (size_t)(l * 3 + 0) * NH, p_rel + (size_t)(l * 3 + 2) * NH,
            ROWA, SRCA, p_rel + (size_t)(l * 3 + 1) * NH,
            AGGP, AGGA);

        // output projection + fused sigmoid-skip mix (merged pair)
        gemm2<<<dim3(1, myA + myP), 256>>>(
            AGGA, 128, out_W + (size_t)(l * 2 + 0) * 128 * 128, 128, out_b + (size_t)(l * 2 + 0) * 128,
            TMPA, nullptr, 128, NA, 1, XA, skipP + (l * 2 + 0),
            AGGP, 128, out_W + (size_t)(l * 2 + 1) * 128 * 128, 128, out_b + (size_t)(l * 2 + 1) * 128,
            TMPP, nullptr, 128, NP, 1, XP, skipP + (l * 2 + 1),
            myA, 2);

        // batch norm: stats then apply (per-layer stats region, pre-zeroed)
        float* ST = STATS + (size_t)l * 512;
        bn_stats2<<<cdiv(NA, 256) + cdiv(NP, 256), 128>>>(TMPA, TMPP, ST);
        float* outA = (l == 1) ? (float*)d_out : XA;
        float* outP = (l == 1) ? (float*)d_out + (size_t)NA * 128 : XP;
        bn_apply2<<<cdiv((long long)(NA + NP) * 128, 256), 256>>>(TMPA, TMPP, ST,
                                                                  bn_gamma + (size_t)l * 128,
                                                                  bn_beta + (size_t)l * 128,
                                                                  outA, outP);
    }
}